// round 2
// baseline (speedup 1.0000x reference)
#include <cuda_runtime.h>
#include <math.h>

#define N_NODES 50000
#define N_EDGES 800000
#define F_INDIM 128
#define HID 256
#define BN_EPS 1e-5f

// ---------------- scratch (device globals: no allocation allowed) ----------------
__device__ int    g_rowptr[N_NODES + 1];
__device__ int    g_cursor[N_NODES];
__device__ int    g_col[N_EDGES];
__device__ float  g_agg[(size_t)N_NODES * HID];
__device__ float  g_hA [(size_t)N_NODES * HID];
__device__ float  g_hB [(size_t)N_NODES * HID];
__device__ double g_stats[2 * HID];   // [0..255]=sum, [256..511]=sumsq

// ---------------- CSR build ----------------
__global__ void zero_counts_kernel() {
    int i = blockIdx.x * blockDim.x + threadIdx.x;
    if (i < N_NODES) g_cursor[i] = 0;
}

__global__ void count_kernel(const int* __restrict__ ei) {
    int e = blockIdx.x * blockDim.x + threadIdx.x;
    if (e < N_EDGES) {
        int d = ei[N_EDGES + e];
        atomicAdd(&g_cursor[d], 1);
    }
}

// single-block chunked Hillis-Steele scan over counts -> exclusive rowptr
__global__ void scan_kernel() {
    __shared__ int sh[1024];
    __shared__ int carry;
    int tid = threadIdx.x;
    if (tid == 0) carry = 0;
    __syncthreads();
    for (int base = 0; base < N_NODES; base += 1024) {
        int i = base + tid;
        int v = (i < N_NODES) ? g_cursor[i] : 0;
        sh[tid] = v;
        __syncthreads();
        for (int off = 1; off < 1024; off <<= 1) {
            int t = (tid >= off) ? sh[tid - off] : 0;
            __syncthreads();
            sh[tid] += t;
            __syncthreads();
        }
        if (i < N_NODES) g_rowptr[i] = carry + sh[tid] - v;   // exclusive
        __syncthreads();
        if (tid == 1023) carry += sh[1023];
        __syncthreads();
    }
    if (tid == 0) g_rowptr[N_NODES] = carry;
}

__global__ void init_cursor_kernel() {
    int i = blockIdx.x * blockDim.x + threadIdx.x;
    if (i < N_NODES) g_cursor[i] = g_rowptr[i];
}

__global__ void scatter_kernel(const int* __restrict__ ei) {
    int e = blockIdx.x * blockDim.x + threadIdx.x;
    if (e < N_EDGES) {
        int s = ei[e];
        int d = ei[N_EDGES + e];
        int pos = atomicAdd(&g_cursor[d], 1);
        g_col[pos] = s;
    }
}

// ---------------- mean aggregation (gather via CSR, 1 warp / node) ----------------
template <int DIN>
__global__ void agg_kernel(const float* __restrict__ xin) {
    int gw   = (blockIdx.x * blockDim.x + threadIdx.x) >> 5;
    int lane = threadIdx.x & 31;
    if (gw >= N_NODES) return;
    int beg = g_rowptr[gw];
    int end = g_rowptr[gw + 1];

    float4 a0 = make_float4(0.f, 0.f, 0.f, 0.f);
    float4 a1 = make_float4(0.f, 0.f, 0.f, 0.f);
    for (int e = beg; e < end; e++) {
        int s = g_col[e];
        const float4* xs = (const float4*)(xin + (size_t)s * DIN);
        float4 v = __ldg(&xs[lane]);
        a0.x += v.x; a0.y += v.y; a0.z += v.z; a0.w += v.w;
        if (DIN == 256) {
            float4 w = __ldg(&xs[lane + 32]);
            a1.x += w.x; a1.y += w.y; a1.z += w.z; a1.w += w.w;
        }
    }
    float inv = 1.0f / fmaxf((float)(end - beg), 1.0f);
    float4* out = (float4*)(g_agg + (size_t)gw * DIN);
    a0.x *= inv; a0.y *= inv; a0.z *= inv; a0.w *= inv;
    out[lane] = a0;
    if (DIN == 256) {
        a1.x *= inv; a1.y *= inv; a1.z *= inv; a1.w *= inv;
        out[lane + 32] = a1;
    }
}

// ---------------- dual-A SGEMM:  C = A0@W0 + A1@W1 + bias  ----------------
// tile: BM=128, BN=64, BK=16, 256 threads, 8x4 per thread
template <int DIN>
__launch_bounds__(256)
__global__ void gemm_kernel(const float* __restrict__ A0, const float* __restrict__ A1,
                            const float* __restrict__ W0, const float* __restrict__ W1,
                            const float* __restrict__ bias, float* __restrict__ C) {
    __shared__ float As[16][132];
    __shared__ float Bs[16][64];

    const int tid = threadIdx.x;
    const int bm  = blockIdx.x * 128;
    const int bn  = blockIdx.y * 64;
    const int tx  = tid & 15;   // col group: cols bn + tx*4 .. +3
    const int ty  = tid >> 4;   // row group: rows bm + ty*8 .. +7

    float acc[8][4];
#pragma unroll
    for (int i = 0; i < 8; i++)
#pragma unroll
        for (int j = 0; j < 4; j++) acc[i][j] = 0.0f;

    const int TOTK = 2 * DIN;
    for (int k0 = 0; k0 < TOTK; k0 += 16) {
        const float* A;
        const float* W;
        int kk;
        if (k0 < DIN) { A = A0; W = W0; kk = k0; }
        else          { A = A1; W = W1; kk = k0 - DIN; }

        // load A tile: 128 rows x 16 k  (2048 elems / 8 per thread)
#pragma unroll
        for (int t = 0; t < 8; t++) {
            int idx = t * 256 + tid;
            int r = idx >> 4;
            int c = idx & 15;
            int grow = bm + r;
            float v = (grow < N_NODES) ? A[(size_t)grow * DIN + kk + c] : 0.0f;
            As[c][r] = v;
        }
        // load B tile: 16 k x 64 cols (1024 elems / 4 per thread)
#pragma unroll
        for (int t = 0; t < 4; t++) {
            int idx = t * 256 + tid;
            int r = idx >> 6;
            int c = idx & 63;
            Bs[r][c] = W[(size_t)(kk + r) * HID + bn + c];
        }
        __syncthreads();

#pragma unroll
        for (int k = 0; k < 16; k++) {
            float rA[8], rB[4];
#pragma unroll
            for (int i = 0; i < 8; i++) rA[i] = As[k][ty * 8 + i];
#pragma unroll
            for (int j = 0; j < 4; j++) rB[j] = Bs[k][tx * 4 + j];
#pragma unroll
            for (int i = 0; i < 8; i++)
#pragma unroll
                for (int j = 0; j < 4; j++) acc[i][j] += rA[i] * rB[j];
        }
        __syncthreads();
    }

    // epilogue: add bias, store
#pragma unroll
    for (int i = 0; i < 8; i++) {
        int grow = bm + ty * 8 + i;
        if (grow < N_NODES) {
#pragma unroll
            for (int j = 0; j < 4; j++) {
                int gcol = bn + tx * 4 + j;
                C[(size_t)grow * HID + gcol] = acc[i][j] + bias[gcol];
            }
        }
    }
}

// ---------------- BN stats (column sum / sumsq) ----------------
__global__ void zero_stats_kernel() {
    int i = threadIdx.x;
    if (i < 2 * HID) g_stats[i] = 0.0;
}

__global__ void stats_kernel(const float* __restrict__ h) {
    int col = threadIdx.x;            // 256 threads = 256 cols
    int r0 = blockIdx.x * 128;
    int r1 = min(r0 + 128, N_NODES);
    float s = 0.0f, s2 = 0.0f;
    for (int r = r0; r < r1; r++) {
        float v = h[(size_t)r * HID + col];
        s += v;
        s2 += v * v;
    }
    atomicAdd(&g_stats[col], (double)s);
    atomicAdd(&g_stats[HID + col], (double)s2);
}

// ---------------- normalize + ELU (in-place safe) ----------------
__global__ void norm_elu_kernel(const float* __restrict__ h,
                                const float* __restrict__ gamma,
                                const float* __restrict__ beta,
                                float* __restrict__ out) {
    __shared__ float sscale[HID];
    __shared__ float sshift[HID];
    int tid = threadIdx.x;   // 256
    {
        double mu  = g_stats[tid] * (1.0 / N_NODES);
        double var = g_stats[HID + tid] * (1.0 / N_NODES) - mu * mu;
        float sc = gamma[tid] * rsqrtf((float)var + BN_EPS);
        sscale[tid] = sc;
        sshift[tid] = beta[tid] - (float)mu * sc;
    }
    __syncthreads();
    int r0 = blockIdx.x * 64;
    int r1 = min(r0 + 64, N_NODES);
    float sc = sscale[tid];
    float sh = sshift[tid];
    for (int r = r0; r < r1; r++) {
        size_t idx = (size_t)r * HID + tid;
        float v = h[idx] * sc + sh;
        out[idx] = (v > 0.0f) ? v : expm1f(v);
    }
}

// ---------------- launch ----------------
extern "C" void kernel_launch(void* const* d_in, const int* in_sizes, int n_in,
                              void* d_out, int out_size) {
    (void)in_sizes; (void)n_in; (void)out_size;
    const float* x  = (const float*)d_in[0];
    const int*   ei = (const int*)d_in[1];   // int64 inputs are delivered as int32 by the harness
    const float* Wn[3] = {(const float*)d_in[2], (const float*)d_in[7],  (const float*)d_in[12]};
    const float* bn[3] = {(const float*)d_in[3], (const float*)d_in[8],  (const float*)d_in[13]};
    const float* Wr[3] = {(const float*)d_in[4], (const float*)d_in[9],  (const float*)d_in[14]};
    const float* gg[3] = {(const float*)d_in[5], (const float*)d_in[10], (const float*)d_in[15]};
    const float* bb[3] = {(const float*)d_in[6], (const float*)d_in[11], (const float*)d_in[16]};
    float* out = (float*)d_out;

    float *agg_p, *hA_p, *hB_p;
    cudaGetSymbolAddress((void**)&agg_p, g_agg);
    cudaGetSymbolAddress((void**)&hA_p,  g_hA);
    cudaGetSymbolAddress((void**)&hB_p,  g_hB);

    const int TB = 256;
    const int nb_nodes = (N_NODES + TB - 1) / TB;
    const int nb_edges = (N_EDGES + TB - 1) / TB;
    const int agg_blocks = (N_NODES * 32 + TB - 1) / TB;
    const int stats_blocks = (N_NODES + 127) / 128;
    const int norm_blocks  = (N_NODES + 63) / 64;
    dim3 gemm_grid((N_NODES + 127) / 128, HID / 64);

    // ---- CSR build (same every call; edge_index is a fixed input) ----
    zero_counts_kernel<<<nb_nodes, TB>>>();
    count_kernel<<<nb_edges, TB>>>(ei);
    scan_kernel<<<1, 1024>>>();
    init_cursor_kernel<<<nb_nodes, TB>>>();
    scatter_kernel<<<nb_edges, TB>>>(ei);

    // ---- layer 0 (d_in = 128) ----
    agg_kernel<F_INDIM><<<agg_blocks, TB>>>(x);
    gemm_kernel<F_INDIM><<<gemm_grid, TB>>>(agg_p, x, Wn[0], Wr[0], bn[0], hA_p);
    zero_stats_kernel<<<1, 512>>>();
    stats_kernel<<<stats_blocks, HID>>>(hA_p);
    norm_elu_kernel<<<norm_blocks, HID>>>(hA_p, gg[0], bb[0], hA_p);

    // ---- layer 1 (d_in = 256) ----
    agg_kernel<HID><<<agg_blocks, TB>>>(hA_p);
    gemm_kernel<HID><<<gemm_grid, TB>>>(agg_p, hA_p, Wn[1], Wr[1], bn[1], hB_p);
    zero_stats_kernel<<<1, 512>>>();
    stats_kernel<<<stats_blocks, HID>>>(hB_p);
    norm_elu_kernel<<<norm_blocks, HID>>>(hB_p, gg[1], bb[1], hB_p);

    // ---- layer 2 (d_in = 256) ----
    agg_kernel<HID><<<agg_blocks, TB>>>(hB_p);
    gemm_kernel<HID><<<gemm_grid, TB>>>(agg_p, hB_p, Wn[2], Wr[2], bn[2], out);
    zero_stats_kernel<<<1, 512>>>();
    stats_kernel<<<stats_blocks, HID>>>(out);
    norm_elu_kernel<<<norm_blocks, HID>>>(out, gg[2], bb[2], out);
}

// round 6
// speedup vs baseline: 1.5784x; 1.5784x over previous
#include <cuda_runtime.h>
#include <cuda_bf16.h>
#include <math.h>
#include <stdint.h>

#define N_NODES 50000
#define N_EDGES 800000
#define F_INDIM 128
#define HID 256
#define BN_EPS 1e-5f

// ---------------- scratch (device globals: no allocation allowed) ----------------
__device__ int    g_rowptr[N_NODES + 1];
__device__ int    g_cursor[N_NODES];
__device__ int    g_col[N_EDGES];
__device__ float  g_h  [(size_t)N_NODES * HID];                 // pre/post-BN activations (fp32)
__device__ unsigned short g_Ahi[(size_t)N_NODES * 512];         // bf16 bits, A matrix (agg | root)
__device__ unsigned short g_Alo[(size_t)N_NODES * 512];
__device__ unsigned short g_Bhi[(size_t)HID * 512];             // bf16 bits, B = [Wn;Wr]^T  [256 x KT]
__device__ unsigned short g_Blo[(size_t)HID * 512];
__device__ double g_stats[2 * HID];

// ---------------- small helpers ----------------
__device__ __forceinline__ unsigned short f2bf_bits(float f) {
    __nv_bfloat16 b = __float2bfloat16(f);
    return *reinterpret_cast<unsigned short*>(&b);
}
__device__ __forceinline__ float bf_bits2f(unsigned short u) {
    __nv_bfloat16 b = *reinterpret_cast<__nv_bfloat16*>(&u);
    return __bfloat162float(b);
}
__device__ __forceinline__ void split_bf(float v, unsigned short& hi, unsigned short& lo) {
    hi = f2bf_bits(v);
    lo = f2bf_bits(v - bf_bits2f(hi));
}
__device__ __forceinline__ uint32_t smem_u32(const void* p) {
    uint32_t a;
    asm("{ .reg .u64 t; cvta.to.shared.u64 t, %1; cvt.u32.u64 %0, t; }" : "=r"(a) : "l"(p));
    return a;
}
__device__ __forceinline__ void cp16(uint32_t dst, const void* src) {
    asm volatile("cp.async.cg.shared.global [%0], [%1], 16;" :: "r"(dst), "l"(src) : "memory");
}
__device__ __forceinline__ void cpa_commit() {
    asm volatile("cp.async.commit_group;" ::: "memory");
}
template <int NN>
__device__ __forceinline__ void cpa_wait() {
    asm volatile("cp.async.wait_group %0;" :: "n"(NN) : "memory");
}
__device__ __forceinline__ void ldm_x4(uint32_t* r, uint32_t addr) {
    asm volatile("ldmatrix.sync.aligned.m8n8.x4.shared.b16 {%0,%1,%2,%3}, [%4];"
                 : "=r"(r[0]), "=r"(r[1]), "=r"(r[2]), "=r"(r[3]) : "r"(addr));
}
__device__ __forceinline__ void mma_bf16(float* d, const uint32_t* a, const uint32_t* b) {
    asm volatile("mma.sync.aligned.m16n8k16.row.col.f32.bf16.bf16.f32 "
                 "{%0,%1,%2,%3}, {%4,%5,%6,%7}, {%8,%9}, {%0,%1,%2,%3};"
                 : "+f"(d[0]), "+f"(d[1]), "+f"(d[2]), "+f"(d[3])
                 : "r"(a[0]), "r"(a[1]), "r"(a[2]), "r"(a[3]), "r"(b[0]), "r"(b[1]));
}

// ---------------- CSR build ----------------
__global__ void zero_counts_kernel() {
    int i = blockIdx.x * blockDim.x + threadIdx.x;
    if (i < N_NODES) g_cursor[i] = 0;
}
__global__ void count_kernel(const int* __restrict__ ei) {
    int e = blockIdx.x * blockDim.x + threadIdx.x;
    if (e < N_EDGES) atomicAdd(&g_cursor[ei[N_EDGES + e]], 1);
}
__global__ void scan_kernel() {
    __shared__ int sh[1024];
    __shared__ int carry;
    int tid = threadIdx.x;
    if (tid == 0) carry = 0;
    __syncthreads();
    for (int base = 0; base < N_NODES; base += 1024) {
        int i = base + tid;
        int v = (i < N_NODES) ? g_cursor[i] : 0;
        sh[tid] = v;
        __syncthreads();
        for (int off = 1; off < 1024; off <<= 1) {
            int t = (tid >= off) ? sh[tid - off] : 0;
            __syncthreads();
            sh[tid] += t;
            __syncthreads();
        }
        if (i < N_NODES) g_rowptr[i] = carry + sh[tid] - v;
        __syncthreads();
        if (tid == 1023) carry += sh[1023];
        __syncthreads();
    }
    if (tid == 0) g_rowptr[N_NODES] = carry;
}
__global__ void init_cursor_kernel() {
    int i = blockIdx.x * blockDim.x + threadIdx.x;
    if (i < N_NODES) g_cursor[i] = g_rowptr[i];
}
__global__ void scatter_kernel(const int* __restrict__ ei) {
    int e = blockIdx.x * blockDim.x + threadIdx.x;
    if (e < N_EDGES) {
        int s = ei[e];
        int d = ei[N_EDGES + e];
        g_col[atomicAdd(&g_cursor[d], 1)] = s;
    }
}

// ---------------- mean aggregation: gather CSR, write bf16 hi/lo into A[:,0:DIN] ----------------
template <int DIN, int KT>
__global__ void agg_kernel(const float* __restrict__ xin) {
    int gw   = (blockIdx.x * blockDim.x + threadIdx.x) >> 5;
    int lane = threadIdx.x & 31;
    if (gw >= N_NODES) return;
    int beg = g_rowptr[gw];
    int end = g_rowptr[gw + 1];

    float4 a0 = make_float4(0.f, 0.f, 0.f, 0.f);
    float4 a1 = make_float4(0.f, 0.f, 0.f, 0.f);
    for (int e = beg; e < end; e++) {
        int s = g_col[e];
        const float4* xs = (const float4*)(xin + (size_t)s * DIN);
        float4 v = __ldg(&xs[lane]);
        a0.x += v.x; a0.y += v.y; a0.z += v.z; a0.w += v.w;
        if (DIN == 256) {
            float4 w = __ldg(&xs[lane + 32]);
            a1.x += w.x; a1.y += w.y; a1.z += w.z; a1.w += w.w;
        }
    }
    float inv = 1.0f / fmaxf((float)(end - beg), 1.0f);
    a0.x *= inv; a0.y *= inv; a0.z *= inv; a0.w *= inv;

    size_t base = (size_t)gw * KT + lane * 4;
    ushort4 hi, lo;
    split_bf(a0.x, hi.x, lo.x); split_bf(a0.y, hi.y, lo.y);
    split_bf(a0.z, hi.z, lo.z); split_bf(a0.w, hi.w, lo.w);
    *(ushort4*)(g_Ahi + base) = hi;
    *(ushort4*)(g_Alo + base) = lo;
    if (DIN == 256) {
        a1.x *= inv; a1.y *= inv; a1.z *= inv; a1.w *= inv;
        split_bf(a1.x, hi.x, lo.x); split_bf(a1.y, hi.y, lo.y);
        split_bf(a1.z, hi.z, lo.z); split_bf(a1.w, hi.w, lo.w);
        *(ushort4*)(g_Ahi + base + 128) = hi;
        *(ushort4*)(g_Alo + base + 128) = lo;
    }
}

// ---------------- convert x into root columns A[:,128:256) (layer 0 only) ----------------
__global__ void convert_x_kernel(const float* __restrict__ x) {
    int i = blockIdx.x * blockDim.x + threadIdx.x;     // over N*32
    if (i >= N_NODES * 32) return;
    int row = i >> 5, grp = i & 31;
    const float4 v = __ldg((const float4*)(x + (size_t)row * 128 + grp * 4));
    size_t base = (size_t)row * 256 + 128 + grp * 4;
    ushort4 hi, lo;
    split_bf(v.x, hi.x, lo.x); split_bf(v.y, hi.y, lo.y);
    split_bf(v.z, hi.z, lo.z); split_bf(v.w, hi.w, lo.w);
    *(ushort4*)(g_Ahi + base) = hi;
    *(ushort4*)(g_Alo + base) = lo;
}

// ---------------- convert weights: B[n][k] = (k<DIN ? Wn[k][n] : Wr[k-DIN][n]) ----------------
template <int DIN, int KT>
__global__ void convert_w_kernel(const float* __restrict__ Wn, const float* __restrict__ Wr) {
    int i = blockIdx.x * blockDim.x + threadIdx.x;    // over 256*KT
    if (i >= HID * KT) return;
    int n = i / KT, k = i % KT;
    float w = (k < DIN) ? Wn[(size_t)k * HID + n] : Wr[(size_t)(k - DIN) * HID + n];
    unsigned short hi, lo;
    split_bf(w, hi, lo);
    g_Bhi[(size_t)n * KT + k] = hi;
    g_Blo[(size_t)n * KT + k] = lo;
}

// ---------------- HMMA split-bf16 GEMM ----------------
// CTA tile 128x128, 8 warps (4x2), warp tile 32x64, K-chunk 32, double-buffered cp.async.
// 3 passes per k-step: Ahi*Bhi + Ahi*Blo + Alo*Bhi  -> fp32 accum.
#define SA 40                        // smem halves per row (32 + 8 pad)
#define TILE_BYTES (128 * SA * 2)    // 10240
#define OF_AHI 0u
#define OF_ALO 10240u
#define OF_BHI 20480u
#define OF_BLO 30720u
#define BUFB   40960u
#define SM_GEMM (2 * 40960)

template <int KT>
__global__ void __launch_bounds__(256, 1)
hmma_gemm_kernel(const unsigned short* __restrict__ Ahi, const unsigned short* __restrict__ Alo,
                 const unsigned short* __restrict__ Bhi, const unsigned short* __restrict__ Blo,
                 const float* __restrict__ bias, float* __restrict__ C) {
    extern __shared__ char smem[];
    const uint32_t sb = smem_u32(smem);
    const int tid  = threadIdx.x;
    const int lane = tid & 31;
    const int wid  = tid >> 5;
    const int wm   = wid & 3;     // 0..3  (m-warp)
    const int wn   = wid >> 2;    // 0..1  (n-warp)
    const int bm   = blockIdx.x * 128;
    const int bn   = blockIdx.y * 128;

    float acc[2][8][4];
#pragma unroll
    for (int a = 0; a < 2; a++)
#pragma unroll
        for (int b = 0; b < 8; b++)
#pragma unroll
            for (int c = 0; c < 4; c++) acc[a][b][c] = 0.0f;

    auto issue = [&](int buf, int k0) {
        uint32_t base = sb + buf * BUFB;
#pragma unroll
        for (int v = 0; v < 2; v++) {
            int idx = v * 256 + tid;       // 0..511
            int r = idx >> 2, s = idx & 3;
            int grow = bm + r;
            if (grow >= N_NODES) grow = N_NODES - 1;   // clamp; discarded in epilogue
            size_t goA = (size_t)grow * KT + k0 + s * 8;
            size_t goB = (size_t)(bn + r) * KT + k0 + s * 8;
            uint32_t d = base + (uint32_t)(r * SA + s * 8) * 2;
            cp16(d + OF_AHI, Ahi + goA);
            cp16(d + OF_ALO, Alo + goA);
            cp16(d + OF_BHI, Bhi + goB);
            cp16(d + OF_BLO, Blo + goB);
        }
    };

    const int nch = KT / 32;
    issue(0, 0);
    cpa_commit();
    int buf = 0;
    for (int ch = 0; ch < nch; ch++) {
        if (ch + 1 < nch) {
            issue(buf ^ 1, (ch + 1) * 32);
            cpa_commit();
            cpa_wait<1>();
        } else {
            cpa_wait<0>();
        }
        __syncthreads();
        uint32_t base = sb + buf * BUFB;
#pragma unroll
        for (int ks = 0; ks < 2; ks++) {
            const int kc = ks * 16;
            uint32_t ah[2][4], al[2][4];
#pragma unroll
            for (int mt = 0; mt < 2; mt++) {
                int row = wm * 32 + mt * 16 + (lane & 15);
                int col = kc + ((lane >> 4) << 3);
                uint32_t ad = base + (uint32_t)(row * SA + col) * 2;
                ldm_x4(ah[mt], ad + OF_AHI);
                ldm_x4(al[mt], ad + OF_ALO);
            }
            uint32_t bh[4][4], bl[4][4];
#pragma unroll
            for (int g = 0; g < 4; g++) {
                int nrow = wn * 64 + g * 16 + ((lane >> 4) << 3) + (lane & 7);
                int kcol = kc + (((lane >> 3) & 1) << 3);
                uint32_t bd = base + (uint32_t)(nrow * SA + kcol) * 2;
                ldm_x4(bh[g], bd + OF_BHI);
                ldm_x4(bl[g], bd + OF_BLO);
            }
#pragma unroll
            for (int mt = 0; mt < 2; mt++)
#pragma unroll
                for (int nt = 0; nt < 8; nt++) {
                    const uint32_t* bhp = &bh[nt >> 1][(nt & 1) * 2];
                    const uint32_t* blp = &bl[nt >> 1][(nt & 1) * 2];
                    mma_bf16(acc[mt][nt], ah[mt], bhp);
                    mma_bf16(acc[mt][nt], ah[mt], blp);
                    mma_bf16(acc[mt][nt], al[mt], bhp);
                }
        }
        __syncthreads();
        buf ^= 1;
    }

    // epilogue: c-frag m16n8: (row = t/4, col = (t%4)*2) and row+8
#pragma unroll
    for (int mt = 0; mt < 2; mt++) {
        int row0 = bm + wm * 32 + mt * 16 + (lane >> 2);
#pragma unroll
        for (int nt = 0; nt < 8; nt++) {
            int col = bn + wn * 64 + nt * 8 + (lane & 3) * 2;
            float b0 = __ldg(&bias[col]);
            float b1 = __ldg(&bias[col + 1]);
            if (row0 < N_NODES) {
                C[(size_t)row0 * HID + col]     = acc[mt][nt][0] + b0;
                C[(size_t)row0 * HID + col + 1] = acc[mt][nt][1] + b1;
            }
            if (row0 + 8 < N_NODES) {
                C[(size_t)(row0 + 8) * HID + col]     = acc[mt][nt][2] + b0;
                C[(size_t)(row0 + 8) * HID + col + 1] = acc[mt][nt][3] + b1;
            }
        }
    }
}

// ---------------- BN stats ----------------
__global__ void zero_stats_kernel() {
    int i = threadIdx.x;
    if (i < 2 * HID) g_stats[i] = 0.0;
}
__global__ void stats_kernel(const float* __restrict__ h) {
    int col = threadIdx.x;
    int r0 = blockIdx.x * 128;
    int r1 = min(r0 + 128, N_NODES);
    float s = 0.0f, s2 = 0.0f;
    for (int r = r0; r < r1; r++) {
        float v = h[(size_t)r * HID + col];
        s += v; s2 += v * v;
    }
    atomicAdd(&g_stats[col], (double)s);
    atomicAdd(&g_stats[HID + col], (double)s2);
}

// ---------------- normalize + ELU; optionally emit bf16 hi/lo root cols for next layer ----------------
__global__ void norm_elu_kernel(const float* __restrict__ h,
                                const float* __restrict__ gamma,
                                const float* __restrict__ beta,
                                float* __restrict__ out,
                                int write_root) {
    __shared__ float sscale[HID];
    __shared__ float sshift[HID];
    int tid = threadIdx.x;   // 256
    {
        double mu  = g_stats[tid] * (1.0 / N_NODES);
        double var = g_stats[HID + tid] * (1.0 / N_NODES) - mu * mu;
        float sc = gamma[tid] * rsqrtf((float)var + BN_EPS);
        sscale[tid] = sc;
        sshift[tid] = beta[tid] - (float)mu * sc;
    }
    __syncthreads();
    int r0 = blockIdx.x * 64;
    int r1 = min(r0 + 64, N_NODES);
    float sc = sscale[tid];
    float sh = sshift[tid];
    for (int r = r0; r < r1; r++) {
        size_t idx = (size_t)r * HID + tid;
        float v = h[idx] * sc + sh;
        float o = (v > 0.0f) ? v : expm1f(v);
        out[idx] = o;
        if (write_root) {
            unsigned short hi, lo;
            split_bf(o, hi, lo);
            size_t a = (size_t)r * 512 + 256 + tid;
            g_Ahi[a] = hi;
            g_Alo[a] = lo;
        }
    }
}

// ---------------- launch ----------------
extern "C" void kernel_launch(void* const* d_in, const int* in_sizes, int n_in,
                              void* d_out, int out_size) {
    (void)in_sizes; (void)n_in; (void)out_size;
    const float* x  = (const float*)d_in[0];
    const int*   ei = (const int*)d_in[1];
    const float* Wn[3] = {(const float*)d_in[2], (const float*)d_in[7],  (const float*)d_in[12]};
    const float* bn[3] = {(const float*)d_in[3], (const float*)d_in[8],  (const float*)d_in[13]};
    const float* Wr[3] = {(const float*)d_in[4], (const float*)d_in[9],  (const float*)d_in[14]};
    const float* gg[3] = {(const float*)d_in[5], (const float*)d_in[10], (const float*)d_in[15]};
    const float* bb[3] = {(const float*)d_in[6], (const float*)d_in[11], (const float*)d_in[16]};
    float* out = (float*)d_out;

    float *h_p;
    unsigned short *Ahi_p, *Alo_p, *Bhi_p, *Blo_p;
    cudaGetSymbolAddress((void**)&h_p,   g_h);
    cudaGetSymbolAddress((void**)&Ahi_p, g_Ahi);
    cudaGetSymbolAddress((void**)&Alo_p, g_Alo);
    cudaGetSymbolAddress((void**)&Bhi_p, g_Bhi);
    cudaGetSymbolAddress((void**)&Blo_p, g_Blo);

    cudaFuncSetAttribute(hmma_gemm_kernel<256>, cudaFuncAttributeMaxDynamicSharedMemorySize, SM_GEMM);
    cudaFuncSetAttribute(hmma_gemm_kernel<512>, cudaFuncAttributeMaxDynamicSharedMemorySize, SM_GEMM);

    const int TB = 256;
    const int nb_nodes = (N_NODES + TB - 1) / TB;
    const int nb_edges = (N_EDGES + TB - 1) / TB;
    const int agg_blocks = (N_NODES * 32 + TB - 1) / TB;
    const int cx_blocks  = (N_NODES * 32 + TB - 1) / TB;
    const int stats_blocks = (N_NODES + 127) / 128;
    const int norm_blocks  = (N_NODES + 63) / 64;
    dim3 gemm_grid((N_NODES + 127) / 128, 2);
    const int cw_blocks_0  = (HID * 256 + TB - 1) / TB;
    const int cw_blocks_12 = (HID * 512 + TB - 1) / TB;

    // ---- CSR build ----
    zero_counts_kernel<<<nb_nodes, TB>>>();
    count_kernel<<<nb_edges, TB>>>(ei);
    scan_kernel<<<1, 1024>>>();
    init_cursor_kernel<<<nb_nodes, TB>>>();
    scatter_kernel<<<nb_edges, TB>>>(ei);

    // ---- layer 0 (DIN=128, KT=256) ----
    agg_kernel<F_INDIM, 256><<<agg_blocks, TB>>>(x);
    convert_x_kernel<<<cx_blocks, TB>>>(x);
    convert_w_kernel<F_INDIM, 256><<<cw_blocks_0, TB>>>(Wn[0], Wr[0]);
    hmma_gemm_kernel<256><<<gemm_grid, 256, SM_GEMM>>>(Ahi_p, Alo_p, Bhi_p, Blo_p, bn[0], h_p);
    zero_stats_kernel<<<1, 512>>>();
    stats_kernel<<<stats_blocks, HID>>>(h_p);
    norm_elu_kernel<<<norm_blocks, HID>>>(h_p, gg[0], bb[0], h_p, 1);

    // ---- layer 1 (DIN=256, KT=512) ----
    agg_kernel<HID, 512><<<agg_blocks, TB>>>(h_p);
    convert_w_kernel<HID, 512><<<cw_blocks_12, TB>>>(Wn[1], Wr[1]);
    hmma_gemm_kernel<512><<<gemm_grid, 256, SM_GEMM>>>(Ahi_p, Alo_p, Bhi_p, Blo_p, bn[1], h_p);
    zero_stats_kernel<<<1, 512>>>();
    stats_kernel<<<stats_blocks, HID>>>(h_p);
    norm_elu_kernel<<<norm_blocks, HID>>>(h_p, gg[1], bb[1], h_p, 1);

    // ---- layer 2 (DIN=256, KT=512) ----
    agg_kernel<HID, 512><<<agg_blocks, TB>>>(h_p);
    convert_w_kernel<HID, 512><<<cw_blocks_12, TB>>>(Wn[2], Wr[2]);
    hmma_gemm_kernel<512><<<gemm_grid, 256, SM_GEMM>>>(Ahi_p, Alo_p, Bhi_p, Blo_p, bn[2], out);
    zero_stats_kernel<<<1, 512>>>();
    stats_kernel<<<stats_blocks, HID>>>(out);
    norm_elu_kernel<<<norm_blocks, HID>>>(out, gg[2], bb[2], out, 0);
}

// round 8
// speedup vs baseline: 1.7738x; 1.1238x over previous
#include <cuda_runtime.h>
#include <cuda_bf16.h>
#include <math.h>
#include <stdint.h>

#define N_NODES 50000
#define N_EDGES 800000
#define F_INDIM 128
#define HID 256
#define BN_EPS 1e-5f

// ---------------- scratch (device globals: no allocation allowed) ----------------
__device__ int    g_rowptr[N_NODES + 1];
__device__ int    g_cursor[N_NODES];
__device__ int    g_col[N_EDGES];
__device__ float  g_h  [(size_t)N_NODES * HID];                 // pre-BN activations (fp32)
__device__ unsigned short g_Ahi[(size_t)N_NODES * 512];         // bf16 bits, A matrix (agg | root)
__device__ unsigned short g_Alo[(size_t)N_NODES * 512];
__device__ unsigned short g_Bhi[(size_t)HID * 512];             // bf16 bits, B = [Wn;Wr]^T  [256 x KT]
__device__ unsigned short g_Blo[(size_t)HID * 512];
__device__ double g_stats[3 * 512];   // per layer: [0..255]=sum, [256..511]=sumsq

// ---------------- small helpers ----------------
__device__ __forceinline__ unsigned short f2bf_bits(float f) {
    __nv_bfloat16 b = __float2bfloat16(f);
    return *reinterpret_cast<unsigned short*>(&b);
}
__device__ __forceinline__ float bf_bits2f(unsigned short u) {
    __nv_bfloat16 b = *reinterpret_cast<__nv_bfloat16*>(&u);
    return __bfloat162float(b);
}
__device__ __forceinline__ void split_bf(float v, unsigned short& hi, unsigned short& lo) {
    hi = f2bf_bits(v);
    lo = f2bf_bits(v - bf_bits2f(hi));
}
__device__ __forceinline__ uint32_t smem_u32(const void* p) {
    uint32_t a;
    asm("{ .reg .u64 t; cvta.to.shared.u64 t, %1; cvt.u32.u64 %0, t; }" : "=r"(a) : "l"(p));
    return a;
}
__device__ __forceinline__ void cp16(uint32_t dst, const void* src) {
    asm volatile("cp.async.cg.shared.global [%0], [%1], 16;" :: "r"(dst), "l"(src) : "memory");
}
__device__ __forceinline__ void cpa_commit() {
    asm volatile("cp.async.commit_group;" ::: "memory");
}
template <int NN>
__device__ __forceinline__ void cpa_wait() {
    asm volatile("cp.async.wait_group %0;" :: "n"(NN) : "memory");
}
__device__ __forceinline__ void ldm_x4(uint32_t* r, uint32_t addr) {
    asm volatile("ldmatrix.sync.aligned.m8n8.x4.shared.b16 {%0,%1,%2,%3}, [%4];"
                 : "=r"(r[0]), "=r"(r[1]), "=r"(r[2]), "=r"(r[3]) : "r"(addr));
}
__device__ __forceinline__ void mma_bf16(float* d, const uint32_t* a, const uint32_t* b) {
    asm volatile("mma.sync.aligned.m16n8k16.row.col.f32.bf16.bf16.f32 "
                 "{%0,%1,%2,%3}, {%4,%5,%6,%7}, {%8,%9}, {%0,%1,%2,%3};"
                 : "+f"(d[0]), "+f"(d[1]), "+f"(d[2]), "+f"(d[3])
                 : "r"(a[0]), "r"(a[1]), "r"(a[2]), "r"(a[3]), "r"(b[0]), "r"(b[1]));
}

// ---------------- prep: zero edge counters + all 3 stats buffers ----------------
__global__ void prep_kernel() {
    int i = blockIdx.x * blockDim.x + threadIdx.x;
    if (i < N_NODES) g_cursor[i] = 0;
    if (i < 3 * 512) g_stats[i] = 0.0;
}
__global__ void count_kernel(const int* __restrict__ ei) {
    int e = blockIdx.x * blockDim.x + threadIdx.x;
    if (e < N_EDGES) atomicAdd(&g_cursor[ei[N_EDGES + e]], 1);
}
// single-block chunked scan over counts -> exclusive rowptr; also re-inits cursor
__global__ void scan_kernel() {
    __shared__ int sh[1024];
    __shared__ int carry;
    int tid = threadIdx.x;
    if (tid == 0) carry = 0;
    __syncthreads();
    for (int base = 0; base < N_NODES; base += 1024) {
        int i = base + tid;
        int v = (i < N_NODES) ? g_cursor[i] : 0;
        sh[tid] = v;
        __syncthreads();
        for (int off = 1; off < 1024; off <<= 1) {
            int t = (tid >= off) ? sh[tid - off] : 0;
            __syncthreads();
            sh[tid] += t;
            __syncthreads();
        }
        if (i < N_NODES) {
            int excl = carry + sh[tid] - v;
            g_rowptr[i] = excl;
            g_cursor[i] = excl;
        }
        __syncthreads();
        if (tid == 1023) carry += sh[1023];
        __syncthreads();
    }
    if (tid == 0) g_rowptr[N_NODES] = carry;
}
__global__ void scatter_kernel(const int* __restrict__ ei) {
    int e = blockIdx.x * blockDim.x + threadIdx.x;
    if (e < N_EDGES) {
        int s = ei[e];
        int d = ei[N_EDGES + e];
        g_col[atomicAdd(&g_cursor[d], 1)] = s;
    }
}

// ---------------- layer0 aggregation: gather fp32 x, write bf16 hi/lo A[:,0:128), KT=256 ----------------
__global__ void agg0_kernel(const float* __restrict__ xin) {
    int gw   = (blockIdx.x * blockDim.x + threadIdx.x) >> 5;
    int lane = threadIdx.x & 31;
    if (gw >= N_NODES) return;
    int beg = g_rowptr[gw];
    int end = g_rowptr[gw + 1];

    float4 a0 = make_float4(0.f, 0.f, 0.f, 0.f);
    for (int e = beg; e < end; e++) {
        int s = g_col[e];
        float4 v = __ldg((const float4*)(xin + (size_t)s * 128) + lane);
        a0.x += v.x; a0.y += v.y; a0.z += v.z; a0.w += v.w;
    }
    float inv = 1.0f / fmaxf((float)(end - beg), 1.0f);
    a0.x *= inv; a0.y *= inv; a0.z *= inv; a0.w *= inv;
    size_t base = (size_t)gw * 256 + lane * 4;
    ushort4 hi, lo;
    split_bf(a0.x, hi.x, lo.x); split_bf(a0.y, hi.y, lo.y);
    split_bf(a0.z, hi.z, lo.z); split_bf(a0.w, hi.w, lo.w);
    *(ushort4*)(g_Ahi + base) = hi;
    *(ushort4*)(g_Alo + base) = lo;
}

// ---------------- layers 1/2 aggregation: gather bf16 hi/lo root cols, write A[:,0:256), KT=512 ----------------
__global__ void agg_bf_kernel() {
    int gw   = (blockIdx.x * blockDim.x + threadIdx.x) >> 5;
    int lane = threadIdx.x & 31;
    if (gw >= N_NODES) return;
    int beg = g_rowptr[gw];
    int end = g_rowptr[gw + 1];

    float a[8] = {0.f, 0.f, 0.f, 0.f, 0.f, 0.f, 0.f, 0.f};
    for (int e = beg; e < end; e++) {
        int s = g_col[e];
        const ushort4* ph = (const ushort4*)(g_Ahi + (size_t)s * 512 + 256);
        const ushort4* pl = (const ushort4*)(g_Alo + (size_t)s * 512 + 256);
        ushort4 h0 = __ldg(&ph[lane]);
        ushort4 l0 = __ldg(&pl[lane]);
        ushort4 h1 = __ldg(&ph[lane + 32]);
        ushort4 l1 = __ldg(&pl[lane + 32]);
        a[0] += bf_bits2f(h0.x) + bf_bits2f(l0.x);
        a[1] += bf_bits2f(h0.y) + bf_bits2f(l0.y);
        a[2] += bf_bits2f(h0.z) + bf_bits2f(l0.z);
        a[3] += bf_bits2f(h0.w) + bf_bits2f(l0.w);
        a[4] += bf_bits2f(h1.x) + bf_bits2f(l1.x);
        a[5] += bf_bits2f(h1.y) + bf_bits2f(l1.y);
        a[6] += bf_bits2f(h1.z) + bf_bits2f(l1.z);
        a[7] += bf_bits2f(h1.w) + bf_bits2f(l1.w);
    }
    float inv = 1.0f / fmaxf((float)(end - beg), 1.0f);
#pragma unroll
    for (int i = 0; i < 8; i++) a[i] *= inv;

    ushort4 hi, lo;
    size_t b0 = (size_t)gw * 512 + lane * 4;
    split_bf(a[0], hi.x, lo.x); split_bf(a[1], hi.y, lo.y);
    split_bf(a[2], hi.z, lo.z); split_bf(a[3], hi.w, lo.w);
    *(ushort4*)(g_Ahi + b0) = hi;
    *(ushort4*)(g_Alo + b0) = lo;
    split_bf(a[4], hi.x, lo.x); split_bf(a[5], hi.y, lo.y);
    split_bf(a[6], hi.z, lo.z); split_bf(a[7], hi.w, lo.w);
    *(ushort4*)(g_Ahi + b0 + 128) = hi;
    *(ushort4*)(g_Alo + b0 + 128) = lo;
}

// ---------------- convert x into root columns A[:,128:256) (layer 0, KT=256) ----------------
__global__ void convert_x_kernel(const float* __restrict__ x) {
    int i = blockIdx.x * blockDim.x + threadIdx.x;     // over N*32
    if (i >= N_NODES * 32) return;
    int row = i >> 5, grp = i & 31;
    const float4 v = __ldg((const float4*)(x + (size_t)row * 128 + grp * 4));
    size_t base = (size_t)row * 256 + 128 + grp * 4;
    ushort4 hi, lo;
    split_bf(v.x, hi.x, lo.x); split_bf(v.y, hi.y, lo.y);
    split_bf(v.z, hi.z, lo.z); split_bf(v.w, hi.w, lo.w);
    *(ushort4*)(g_Ahi + base) = hi;
    *(ushort4*)(g_Alo + base) = lo;
}

// ---------------- convert weights: B[n][k] = (k<DIN ? Wn[k][n] : Wr[k-DIN][n]) ----------------
template <int DIN, int KT>
__global__ void convert_w_kernel(const float* __restrict__ Wn, const float* __restrict__ Wr) {
    int i = blockIdx.x * blockDim.x + threadIdx.x;    // over 256*KT
    if (i >= HID * KT) return;
    int n = i / KT, k = i % KT;
    float w = (k < DIN) ? Wn[(size_t)k * HID + n] : Wr[(size_t)(k - DIN) * HID + n];
    unsigned short hi, lo;
    split_bf(w, hi, lo);
    g_Bhi[(size_t)n * KT + k] = hi;
    g_Blo[(size_t)n * KT + k] = lo;
}

// ---------------- HMMA split-bf16 GEMM with fused BN-stats epilogue ----------------
// CTA tile 128x128, 8 warps (4x2), warp tile 32x64, K-chunk 32, double-buffered cp.async.
// 3 passes per k-step: Ahi*Bhi + Ahi*Blo + Alo*Bhi  -> fp32 accum.
#define SA 40                        // smem halves per row (32 + 8 pad)
#define OF_AHI 0u
#define OF_ALO 10240u
#define OF_BHI 20480u
#define OF_BLO 30720u
#define BUFB   40960u
#define SM_GEMM (2 * 40960)

template <int KT>
__global__ void __launch_bounds__(256, 2)
hmma_gemm_kernel(const unsigned short* __restrict__ Ahi, const unsigned short* __restrict__ Alo,
                 const unsigned short* __restrict__ Bhi, const unsigned short* __restrict__ Blo,
                 const float* __restrict__ bias, float* __restrict__ C,
                 double* __restrict__ stats) {
    extern __shared__ char smem[];
    const uint32_t sb = smem_u32(smem);
    const int tid  = threadIdx.x;
    const int lane = tid & 31;
    const int wid  = tid >> 5;
    const int wm   = wid & 3;     // 0..3  (m-warp)
    const int wn   = wid >> 2;    // 0..1  (n-warp)
    const int bm   = blockIdx.x * 128;
    const int bn   = blockIdx.y * 128;

    float acc[2][8][4];
#pragma unroll
    for (int a = 0; a < 2; a++)
#pragma unroll
        for (int b = 0; b < 8; b++)
#pragma unroll
            for (int c = 0; c < 4; c++) acc[a][b][c] = 0.0f;

    auto issue = [&](int buf, int k0) {
        uint32_t base = sb + buf * BUFB;
#pragma unroll
        for (int v = 0; v < 2; v++) {
            int idx = v * 256 + tid;       // 0..511
            int r = idx >> 2, s = idx & 3;
            int grow = bm + r;
            if (grow >= N_NODES) grow = N_NODES - 1;   // clamp; excluded in epilogue
            size_t goA = (size_t)grow * KT + k0 + s * 8;
            size_t goB = (size_t)(bn + r) * KT + k0 + s * 8;
            uint32_t d = base + (uint32_t)(r * SA + s * 8) * 2;
            cp16(d + OF_AHI, Ahi + goA);
            cp16(d + OF_ALO, Alo + goA);
            cp16(d + OF_BHI, Bhi + goB);
            cp16(d + OF_BLO, Blo + goB);
        }
    };

    const int nch = KT / 32;
    issue(0, 0);
    cpa_commit();
    int buf = 0;
    for (int ch = 0; ch < nch; ch++) {
        if (ch + 1 < nch) {
            issue(buf ^ 1, (ch + 1) * 32);
            cpa_commit();
            cpa_wait<1>();
        } else {
            cpa_wait<0>();
        }
        __syncthreads();
        uint32_t base = sb + buf * BUFB;
#pragma unroll
        for (int ks = 0; ks < 2; ks++) {
            const int kc = ks * 16;
            uint32_t ah[2][4], al[2][4];
#pragma unroll
            for (int mt = 0; mt < 2; mt++) {
                int row = wm * 32 + mt * 16 + (lane & 15);
                int col = kc + ((lane >> 4) << 3);
                uint32_t ad = base + (uint32_t)(row * SA + col) * 2;
                ldm_x4(ah[mt], ad + OF_AHI);
                ldm_x4(al[mt], ad + OF_ALO);
            }
#pragma unroll
            for (int g = 0; g < 4; g++) {          // 16-col group: low B-frag register footprint
                int nrow = wn * 64 + g * 16 + ((lane >> 4) << 3) + (lane & 7);
                int kcol = kc + (((lane >> 3) & 1) << 3);
                uint32_t bd = base + (uint32_t)(nrow * SA + kcol) * 2;
                uint32_t bh4[4], bl4[4];
                ldm_x4(bh4, bd + OF_BHI);
                ldm_x4(bl4, bd + OF_BLO);
#pragma unroll
                for (int mt = 0; mt < 2; mt++)
#pragma unroll
                    for (int s = 0; s < 2; s++) {
                        int nt = g * 2 + s;
                        mma_bf16(acc[mt][nt], ah[mt], &bh4[s * 2]);
                        mma_bf16(acc[mt][nt], ah[mt], &bl4[s * 2]);
                        mma_bf16(acc[mt][nt], al[mt], &bh4[s * 2]);
                    }
            }
        }
        __syncthreads();
        buf ^= 1;
    }

    // ---- epilogue: write C (+bias) and fused BN column stats ----
    float* ssum = (float*)smem;          // [128]
    float* ssq  = ssum + 128;            // [128]
    if (tid < 128) { ssum[tid] = 0.0f; ssq[tid] = 0.0f; }
    __syncthreads();

#pragma unroll
    for (int nt = 0; nt < 8; nt++) {
        int col = bn + wn * 64 + nt * 8 + (lane & 3) * 2;
        float b0 = __ldg(&bias[col]);
        float b1 = __ldg(&bias[col + 1]);
        float p0 = 0.f, p1 = 0.f, q0 = 0.f, q1 = 0.f;
#pragma unroll
        for (int mt = 0; mt < 2; mt++) {
            int row0 = bm + wm * 32 + mt * 16 + (lane >> 2);
            float c0 = acc[mt][nt][0] + b0;
            float c1 = acc[mt][nt][1] + b1;
            float c2 = acc[mt][nt][2] + b0;
            float c3 = acc[mt][nt][3] + b1;
            if (row0 < N_NODES) {
                C[(size_t)row0 * HID + col]     = c0;
                C[(size_t)row0 * HID + col + 1] = c1;
                p0 += c0; q0 += c0 * c0;
                p1 += c1; q1 += c1 * c1;
            }
            if (row0 + 8 < N_NODES) {
                C[(size_t)(row0 + 8) * HID + col]     = c2;
                C[(size_t)(row0 + 8) * HID + col + 1] = c3;
                p0 += c2; q0 += c2 * c2;
                p1 += c3; q1 += c3 * c3;
            }
        }
        // reduce over the 8 lanes sharing (lane & 3)
#pragma unroll
        for (int m = 4; m < 32; m <<= 1) {
            p0 += __shfl_xor_sync(0xFFFFFFFFu, p0, m);
            p1 += __shfl_xor_sync(0xFFFFFFFFu, p1, m);
            q0 += __shfl_xor_sync(0xFFFFFFFFu, q0, m);
            q1 += __shfl_xor_sync(0xFFFFFFFFu, q1, m);
        }
        if (lane < 4) {
            int lc = wn * 64 + nt * 8 + lane * 2;
            atomicAdd(&ssum[lc], p0);     atomicAdd(&ssq[lc], q0);
            atomicAdd(&ssum[lc + 1], p1); atomicAdd(&ssq[lc + 1], q1);
        }
    }
    __syncthreads();
    if (tid < 128) {
        int col = bn + tid;
        atomicAdd(&stats[col],       (double)ssum[tid]);
        atomicAdd(&stats[256 + col], (double)ssq[tid]);
    }
}

// ---------------- normalize + ELU ----------------
// write_mode: 0 = root cols only (layers 0/1), 1 = fp32 out only (final layer)
__global__ void norm_elu_kernel(const float* __restrict__ h,
                                const float* __restrict__ gamma,
                                const float* __restrict__ beta,
                                const double* __restrict__ stats,
                                float* __restrict__ out,
                                int write_mode) {
    __shared__ float sscale[HID];
    __shared__ float sshift[HID];
    int tid = threadIdx.x;   // 256
    {
        double mu  = stats[tid] * (1.0 / N_NODES);
        double var = stats[256 + tid] * (1.0 / N_NODES) - mu * mu;
        float sc = gamma[tid] * rsqrtf((float)var + BN_EPS);
        sscale[tid] = sc;
        sshift[tid] = beta[tid] - (float)mu * sc;
    }
    __syncthreads();
    int r0 = blockIdx.x * 64;
    int r1 = min(r0 + 64, N_NODES);
    float sc = sscale[tid];
    float sh = sshift[tid];
    for (int r = r0; r < r1; r++) {
        size_t idx = (size_t)r * HID + tid;
        float v = h[idx] * sc + sh;
        float o = (v > 0.0f) ? v : expm1f(v);
        if (write_mode == 1) {
            out[idx] = o;
        } else {
            unsigned short hi, lo;
            split_bf(o, hi, lo);
            size_t a = (size_t)r * 512 + 256 + tid;
            g_Ahi[a] = hi;
            g_Alo[a] = lo;
        }
    }
}

// ---------------- launch ----------------
extern "C" void kernel_launch(void* const* d_in, const int* in_sizes, int n_in,
                              void* d_out, int out_size) {
    (void)in_sizes; (void)n_in; (void)out_size;
    const float* x  = (const float*)d_in[0];
    const int*   ei = (const int*)d_in[1];
    const float* Wn[3] = {(const float*)d_in[2], (const float*)d_in[7],  (const float*)d_in[12]};
    const float* bn[3] = {(const float*)d_in[3], (const float*)d_in[8],  (const float*)d_in[13]};
    const float* Wr[3] = {(const float*)d_in[4], (const float*)d_in[9],  (const float*)d_in[14]};
    const float* gg[3] = {(const float*)d_in[5], (const float*)d_in[10], (const float*)d_in[15]};
    const float* bb[3] = {(const float*)d_in[6], (const float*)d_in[11], (const float*)d_in[16]};
    float* out = (float*)d_out;

    float *h_p;
    double *stats_p;
    unsigned short *Ahi_p, *Alo_p, *Bhi_p, *Blo_p;
    cudaGetSymbolAddress((void**)&h_p,    g_h);
    cudaGetSymbolAddress((void**)&stats_p, g_stats);
    cudaGetSymbolAddress((void**)&Ahi_p,  g_Ahi);
    cudaGetSymbolAddress((void**)&Alo_p,  g_Alo);
    cudaGetSymbolAddress((void**)&Bhi_p,  g_Bhi);
    cudaGetSymbolAddress((void**)&Blo_p,  g_Blo);

    cudaFuncSetAttribute(hmma_gemm_kernel<256>, cudaFuncAttributeMaxDynamicSharedMemorySize, SM_GEMM);
    cudaFuncSetAttribute(hmma_gemm_kernel<512>, cudaFuncAttributeMaxDynamicSharedMemorySize, SM_GEMM);

    const int TB = 256;
    const int nb_nodes = (N_NODES + TB - 1) / TB;
    const int nb_edges = (N_EDGES + TB - 1) / TB;
    const int agg_blocks = (N_NODES * 32 + TB - 1) / TB;
    const int cx_blocks  = (N_NODES * 32 + TB - 1) / TB;
    const int norm_blocks = (N_NODES + 63) / 64;
    dim3 gemm_grid((N_NODES + 127) / 128, 2);
    const int cw_blocks_0  = (HID * 256 + TB - 1) / TB;
    const int cw_blocks_12 = (HID * 512 + TB - 1) / TB;

    // ---- CSR build + zeroing ----
    prep_kernel<<<nb_nodes, TB>>>();
    count_kernel<<<nb_edges, TB>>>(ei);
    scan_kernel<<<1, 1024>>>();
    scatter_kernel<<<nb_edges, TB>>>(ei);

    // ---- layer 0 (DIN=128, KT=256) ----
    agg0_kernel<<<agg_blocks, TB>>>(x);
    convert_x_kernel<<<cx_blocks, TB>>>(x);
    convert_w_kernel<F_INDIM, 256><<<cw_blocks_0, TB>>>(Wn[0], Wr[0]);
    hmma_gemm_kernel<256><<<gemm_grid, 256, SM_GEMM>>>(Ahi_p, Alo_p, Bhi_p, Blo_p, bn[0], h_p, stats_p);
    norm_elu_kernel<<<norm_blocks, HID>>>(h_p, gg[0], bb[0], stats_p, nullptr, 0);

    // ---- layer 1 (DIN=256, KT=512) ----
    agg_bf_kernel<<<agg_blocks, TB>>>();
    convert_w_kernel<HID, 512><<<cw_blocks_12, TB>>>(Wn[1], Wr[1]);
    hmma_gemm_kernel<512><<<gemm_grid, 256, SM_GEMM>>>(Ahi_p, Alo_p, Bhi_p, Blo_p, bn[1], h_p, stats_p + 512);
    norm_elu_kernel<<<norm_blocks, HID>>>(h_p, gg[1], bb[1], stats_p + 512, nullptr, 0);

    // ---- layer 2 (DIN=256, KT=512) ----
    agg_bf_kernel<<<agg_blocks, TB>>>();
    convert_w_kernel<HID, 512><<<cw_blocks_12, TB>>>(Wn[2], Wr[2]);
    hmma_gemm_kernel<512><<<gemm_grid, 256, SM_GEMM>>>(Ahi_p, Alo_p, Bhi_p, Blo_p, bn[2], out, stats_p + 1024);
    norm_elu_kernel<<<norm_blocks, HID>>>(out, gg[2], bb[2], stats_p + 1024, out, 1);
}

// round 9
// speedup vs baseline: 2.0675x; 1.1656x over previous
#include <cuda_runtime.h>
#include <cuda_bf16.h>
#include <cuda_fp16.h>
#include <math.h>
#include <stdint.h>

#define N_NODES 50000
#define N_EDGES 800000
#define F_INDIM 128
#define HID 256
#define BN_EPS 1e-5f
#define SCAN_NB 49   // ceil(50000/1024)

// ---------------- scratch (device globals: no allocation allowed) ----------------
__device__ int    g_rowptr[N_NODES + 1];
__device__ int    g_cursor[N_NODES];
__device__ int    g_bsum[64];
__device__ int    g_col[N_EDGES];
__device__ float  g_h  [(size_t)N_NODES * HID];                 // pre-BN activations (fp32)
__device__ unsigned short g_Ahi[(size_t)N_NODES * 512];         // bf16 bits, A matrix (agg | root)
__device__ unsigned short g_Alo[(size_t)N_NODES * 512];
__device__ unsigned short g_Bhi[(size_t)HID * 512];             // bf16 bits, B = [Wn;Wr]^T
__device__ unsigned short g_Blo[(size_t)HID * 512];
__device__ __half g_xh   [(size_t)N_NODES * F_INDIM];           // fp16 copy of x (gather source, L0)
__device__ __half g_rooth[(size_t)N_NODES * HID];               // fp16 activations (gather source, L1/L2)
__device__ double g_stats[3 * 512];   // per layer: [0..255]=sum, [256..511]=sumsq

// ---------------- small helpers ----------------
__device__ __forceinline__ unsigned short f2bf_bits(float f) {
    __nv_bfloat16 b = __float2bfloat16(f);
    return *reinterpret_cast<unsigned short*>(&b);
}
__device__ __forceinline__ float bf_bits2f(unsigned short u) {
    __nv_bfloat16 b = *reinterpret_cast<__nv_bfloat16*>(&u);
    return __bfloat162float(b);
}
__device__ __forceinline__ void split_bf(float v, unsigned short& hi, unsigned short& lo) {
    hi = f2bf_bits(v);
    lo = f2bf_bits(v - bf_bits2f(hi));
}
__device__ __forceinline__ uint32_t smem_u32(const void* p) {
    uint32_t a;
    asm("{ .reg .u64 t; cvta.to.shared.u64 t, %1; cvt.u32.u64 %0, t; }" : "=r"(a) : "l"(p));
    return a;
}
__device__ __forceinline__ void cp16(uint32_t dst, const void* src) {
    asm volatile("cp.async.cg.shared.global [%0], [%1], 16;" :: "r"(dst), "l"(src) : "memory");
}
__device__ __forceinline__ void cpa_commit() {
    asm volatile("cp.async.commit_group;" ::: "memory");
}
template <int NN>
__device__ __forceinline__ void cpa_wait() {
    asm volatile("cp.async.wait_group %0;" :: "n"(NN) : "memory");
}
__device__ __forceinline__ void ldm_x4(uint32_t* r, uint32_t addr) {
    asm volatile("ldmatrix.sync.aligned.m8n8.x4.shared.b16 {%0,%1,%2,%3}, [%4];"
                 : "=r"(r[0]), "=r"(r[1]), "=r"(r[2]), "=r"(r[3]) : "r"(addr));
}
__device__ __forceinline__ void mma_bf16(float* d, const uint32_t* a, const uint32_t* b) {
    asm volatile("mma.sync.aligned.m16n8k16.row.col.f32.bf16.bf16.f32 "
                 "{%0,%1,%2,%3}, {%4,%5,%6,%7}, {%8,%9}, {%0,%1,%2,%3};"
                 : "+f"(d[0]), "+f"(d[1]), "+f"(d[2]), "+f"(d[3])
                 : "r"(a[0]), "r"(a[1]), "r"(a[2]), "r"(a[3]), "r"(b[0]), "r"(b[1]));
}

// ---------------- prep: zero edge counters + all 3 stats buffers ----------------
__global__ void prep_kernel() {
    int i = blockIdx.x * blockDim.x + threadIdx.x;
    if (i < N_NODES) g_cursor[i] = 0;
    if (i < 3 * 512) g_stats[i] = 0.0;
}
__global__ void count_kernel(const int* __restrict__ ei) {
    int e = blockIdx.x * blockDim.x + threadIdx.x;
    if (e < N_EDGES) atomicAdd(&g_cursor[ei[N_EDGES + e]], 1);
}
// ---- multi-block scan: phase 1 (per-block exclusive scan + block sums) ----
__global__ void scan1_kernel() {
    __shared__ int sh[1024];
    int tid = threadIdx.x;
    int i = blockIdx.x * 1024 + tid;
    int v = (i < N_NODES) ? g_cursor[i] : 0;
    sh[tid] = v;
    __syncthreads();
    for (int off = 1; off < 1024; off <<= 1) {
        int t = (tid >= off) ? sh[tid - off] : 0;
        __syncthreads();
        sh[tid] += t;
        __syncthreads();
    }
    if (i < N_NODES) g_rowptr[i] = sh[tid] - v;     // local exclusive
    if (tid == 1023) g_bsum[blockIdx.x] = sh[1023];
}
// ---- phase 2: scan the 49 block sums (1 block, 64 threads) ----
__global__ void scan2_kernel() {
    __shared__ int sh[64];
    int tid = threadIdx.x;
    int v = (tid < SCAN_NB) ? g_bsum[tid] : 0;
    sh[tid] = v;
    __syncthreads();
    for (int off = 1; off < 64; off <<= 1) {
        int t = (tid >= off) ? sh[tid - off] : 0;
        __syncthreads();
        sh[tid] += t;
        __syncthreads();
    }
    if (tid < SCAN_NB) g_bsum[tid] = sh[tid] - v;   // exclusive block offsets
    if (tid == 63) g_rowptr[N_NODES] = sh[63];
}
// ---- phase 3: add block offsets, init cursor ----
__global__ void scan3_kernel() {
    int i = blockIdx.x * 1024 + threadIdx.x;
    if (i < N_NODES) {
        int r = g_rowptr[i] + g_bsum[blockIdx.x];
        g_rowptr[i] = r;
        g_cursor[i] = r;
    }
}
__global__ void scatter_kernel(const int* __restrict__ ei) {
    int e = blockIdx.x * blockDim.x + threadIdx.x;
    if (e < N_EDGES) {
        int s = ei[e];
        int d = ei[N_EDGES + e];
        g_col[atomicAdd(&g_cursor[d], 1)] = s;
    }
}

// ---------------- convert x: fp16 gather copy + bf16 hi/lo root cols A[:,128:256) ----------------
__global__ void convert_x_kernel(const float* __restrict__ x) {
    int i = blockIdx.x * blockDim.x + threadIdx.x;     // over N*32
    if (i >= N_NODES * 32) return;
    int row = i >> 5, grp = i & 31;
    const float4 v = __ldg((const float4*)(x + (size_t)row * 128 + grp * 4));
    // fp16 copy for gathering
    __half2 h01 = __floats2half2_rn(v.x, v.y);
    __half2 h23 = __floats2half2_rn(v.z, v.w);
    uint2 u;
    u.x = *reinterpret_cast<uint32_t*>(&h01);
    u.y = *reinterpret_cast<uint32_t*>(&h23);
    *(uint2*)(g_xh + (size_t)row * 128 + grp * 4) = u;
    // bf16 hi/lo root columns
    size_t base = (size_t)row * 256 + 128 + grp * 4;
    ushort4 hi, lo;
    split_bf(v.x, hi.x, lo.x); split_bf(v.y, hi.y, lo.y);
    split_bf(v.z, hi.z, lo.z); split_bf(v.w, hi.w, lo.w);
    *(ushort4*)(g_Ahi + base) = hi;
    *(ushort4*)(g_Alo + base) = lo;
}

// ---------------- layer0 aggregation: gather fp16 x, write bf16 hi/lo A[:,0:128), KT=256 ----------------
__global__ void agg0_kernel() {
    int gw   = (blockIdx.x * blockDim.x + threadIdx.x) >> 5;
    int lane = threadIdx.x & 31;
    if (gw >= N_NODES) return;
    int beg = g_rowptr[gw];
    int end = g_rowptr[gw + 1];

    float a[4] = {0.f, 0.f, 0.f, 0.f};
    for (int e = beg; e < end; e++) {
        int s = g_col[e];
        uint2 u = __ldg((const uint2*)(g_xh + (size_t)s * 128) + lane);
        __half2 h01 = *reinterpret_cast<__half2*>(&u.x);
        __half2 h23 = *reinterpret_cast<__half2*>(&u.y);
        float2 f01 = __half22float2(h01);
        float2 f23 = __half22float2(h23);
        a[0] += f01.x; a[1] += f01.y; a[2] += f23.x; a[3] += f23.y;
    }
    float inv = 1.0f / fmaxf((float)(end - beg), 1.0f);
#pragma unroll
    for (int i = 0; i < 4; i++) a[i] *= inv;
    size_t base = (size_t)gw * 256 + lane * 4;
    ushort4 hi, lo;
    split_bf(a[0], hi.x, lo.x); split_bf(a[1], hi.y, lo.y);
    split_bf(a[2], hi.z, lo.z); split_bf(a[3], hi.w, lo.w);
    *(ushort4*)(g_Ahi + base) = hi;
    *(ushort4*)(g_Alo + base) = lo;
}

// ---------------- layers 1/2 aggregation: gather fp16 activations, write A[:,0:256), KT=512 ----------------
__global__ void agg_bf_kernel() {
    int gw   = (blockIdx.x * blockDim.x + threadIdx.x) >> 5;
    int lane = threadIdx.x & 31;
    if (gw >= N_NODES) return;
    int beg = g_rowptr[gw];
    int end = g_rowptr[gw + 1];

    float a[8] = {0.f, 0.f, 0.f, 0.f, 0.f, 0.f, 0.f, 0.f};
    for (int e = beg; e < end; e++) {
        int s = g_col[e];
        uint4 u = __ldg((const uint4*)(g_rooth + (size_t)s * 256) + lane);   // 8 halves
        __half2 h0 = *reinterpret_cast<__half2*>(&u.x);
        __half2 h1 = *reinterpret_cast<__half2*>(&u.y);
        __half2 h2 = *reinterpret_cast<__half2*>(&u.z);
        __half2 h3 = *reinterpret_cast<__half2*>(&u.w);
        float2 f0 = __half22float2(h0), f1 = __half22float2(h1);
        float2 f2 = __half22float2(h2), f3 = __half22float2(h3);
        a[0] += f0.x; a[1] += f0.y; a[2] += f1.x; a[3] += f1.y;
        a[4] += f2.x; a[5] += f2.y; a[6] += f3.x; a[7] += f3.y;
    }
    float inv = 1.0f / fmaxf((float)(end - beg), 1.0f);
#pragma unroll
    for (int i = 0; i < 8; i++) a[i] *= inv;

    size_t b0 = (size_t)gw * 512 + lane * 8;    // cols lane*8 .. +7
    ushort4 hi, lo;
    split_bf(a[0], hi.x, lo.x); split_bf(a[1], hi.y, lo.y);
    split_bf(a[2], hi.z, lo.z); split_bf(a[3], hi.w, lo.w);
    *(ushort4*)(g_Ahi + b0) = hi;
    *(ushort4*)(g_Alo + b0) = lo;
    split_bf(a[4], hi.x, lo.x); split_bf(a[5], hi.y, lo.y);
    split_bf(a[6], hi.z, lo.z); split_bf(a[7], hi.w, lo.w);
    *(ushort4*)(g_Ahi + b0 + 4) = hi;
    *(ushort4*)(g_Alo + b0 + 4) = lo;
}

// ---------------- convert weights: B[n][k] = (k<DIN ? Wn[k][n] : Wr[k-DIN][n]) ----------------
template <int DIN, int KT>
__global__ void convert_w_kernel(const float* __restrict__ Wn, const float* __restrict__ Wr) {
    int i = blockIdx.x * blockDim.x + threadIdx.x;    // over 256*KT
    if (i >= HID * KT) return;
    int n = i / KT, k = i % KT;
    float w = (k < DIN) ? Wn[(size_t)k * HID + n] : Wr[(size_t)(k - DIN) * HID + n];
    unsigned short hi, lo;
    split_bf(w, hi, lo);
    g_Bhi[(size_t)n * KT + k] = hi;
    g_Blo[(size_t)n * KT + k] = lo;
}

// ---------------- HMMA split-bf16 GEMM with fused BN-stats epilogue ----------------
// CTA tile 128x128, 8 warps (4x2), warp tile 32x64, K-chunk 32, double-buffered cp.async.
// 3 passes per k-step: Ahi*Bhi + Ahi*Blo + Alo*Bhi  -> fp32 accum.
#define SA 40                        // smem halves per row (32 + 8 pad)
#define OF_AHI 0u
#define OF_ALO 10240u
#define OF_BHI 20480u
#define OF_BLO 30720u
#define BUFB   40960u
#define SM_GEMM (2 * 40960)

template <int KT>
__global__ void __launch_bounds__(256, 2)
hmma_gemm_kernel(const unsigned short* __restrict__ Ahi, const unsigned short* __restrict__ Alo,
                 const unsigned short* __restrict__ Bhi, const unsigned short* __restrict__ Blo,
                 const float* __restrict__ bias, float* __restrict__ C,
                 double* __restrict__ stats) {
    extern __shared__ char smem[];
    const uint32_t sb = smem_u32(smem);
    const int tid  = threadIdx.x;
    const int lane = tid & 31;
    const int wid  = tid >> 5;
    const int wm   = wid & 3;
    const int wn   = wid >> 2;
    const int bm   = blockIdx.x * 128;
    const int bn   = blockIdx.y * 128;

    float acc[2][8][4];
#pragma unroll
    for (int a = 0; a < 2; a++)
#pragma unroll
        for (int b = 0; b < 8; b++)
#pragma unroll
            for (int c = 0; c < 4; c++) acc[a][b][c] = 0.0f;

    auto issue = [&](int buf, int k0) {
        uint32_t base = sb + buf * BUFB;
#pragma unroll
        for (int v = 0; v < 2; v++) {
            int idx = v * 256 + tid;
            int r = idx >> 2, s = idx & 3;
            int grow = bm + r;
            if (grow >= N_NODES) grow = N_NODES - 1;   // clamp; excluded in epilogue
            size_t goA = (size_t)grow * KT + k0 + s * 8;
            size_t goB = (size_t)(bn + r) * KT + k0 + s * 8;
            uint32_t d = base + (uint32_t)(r * SA + s * 8) * 2;
            cp16(d + OF_AHI, Ahi + goA);
            cp16(d + OF_ALO, Alo + goA);
            cp16(d + OF_BHI, Bhi + goB);
            cp16(d + OF_BLO, Blo + goB);
        }
    };

    const int nch = KT / 32;
    issue(0, 0);
    cpa_commit();
    int buf = 0;
    for (int ch = 0; ch < nch; ch++) {
        if (ch + 1 < nch) {
            issue(buf ^ 1, (ch + 1) * 32);
            cpa_commit();
            cpa_wait<1>();
        } else {
            cpa_wait<0>();
        }
        __syncthreads();
        uint32_t base = sb + buf * BUFB;
#pragma unroll
        for (int ks = 0; ks < 2; ks++) {
            const int kc = ks * 16;
            uint32_t ah[2][4], al[2][4];
#pragma unroll
            for (int mt = 0; mt < 2; mt++) {
                int row = wm * 32 + mt * 16 + (lane & 15);
                int col = kc + ((lane >> 4) << 3);
                uint32_t ad = base + (uint32_t)(row * SA + col) * 2;
                ldm_x4(ah[mt], ad + OF_AHI);
                ldm_x4(al[mt], ad + OF_ALO);
            }
#pragma unroll
            for (int g = 0; g < 4; g++) {
                int nrow = wn * 64 + g * 16 + ((lane >> 4) << 3) + (lane & 7);
                int kcol = kc + (((lane >> 3) & 1) << 3);
                uint32_t bd = base + (uint32_t)(nrow * SA + kcol) * 2;
                uint32_t bh4[4], bl4[4];
                ldm_x4(bh4, bd + OF_BHI);
                ldm_x4(bl4, bd + OF_BLO);
#pragma unroll
                for (int mt = 0; mt < 2; mt++)
#pragma unroll
                    for (int s = 0; s < 2; s++) {
                        int nt = g * 2 + s;
                        mma_bf16(acc[mt][nt], ah[mt], &bh4[s * 2]);
                        mma_bf16(acc[mt][nt], ah[mt], &bl4[s * 2]);
                        mma_bf16(acc[mt][nt], al[mt], &bh4[s * 2]);
                    }
            }
        }
        __syncthreads();
        buf ^= 1;
    }

    // ---- epilogue: write C (+bias) and fused BN column stats ----
    float* ssum = (float*)smem;
    float* ssq  = ssum + 128;
    if (tid < 128) { ssum[tid] = 0.0f; ssq[tid] = 0.0f; }
    __syncthreads();

#pragma unroll
    for (int nt = 0; nt < 8; nt++) {
        int col = bn + wn * 64 + nt * 8 + (lane & 3) * 2;
        float b0 = __ldg(&bias[col]);
        float b1 = __ldg(&bias[col + 1]);
        float p0 = 0.f, p1 = 0.f, q0 = 0.f, q1 = 0.f;
#pragma unroll
        for (int mt = 0; mt < 2; mt++) {
            int row0 = bm + wm * 32 + mt * 16 + (lane >> 2);
            float c0 = acc[mt][nt][0] + b0;
            float c1 = acc[mt][nt][1] + b1;
            float c2 = acc[mt][nt][2] + b0;
            float c3 = acc[mt][nt][3] + b1;
            if (row0 < N_NODES) {
                C[(size_t)row0 * HID + col]     = c0;
                C[(size_t)row0 * HID + col + 1] = c1;
                p0 += c0; q0 += c0 * c0;
                p1 += c1; q1 += c1 * c1;
            }
            if (row0 + 8 < N_NODES) {
                C[(size_t)(row0 + 8) * HID + col]     = c2;
                C[(size_t)(row0 + 8) * HID + col + 1] = c3;
                p0 += c2; q0 += c2 * c2;
                p1 += c3; q1 += c3 * c3;
            }
        }
#pragma unroll
        for (int m = 4; m < 32; m <<= 1) {
            p0 += __shfl_xor_sync(0xFFFFFFFFu, p0, m);
            p1 += __shfl_xor_sync(0xFFFFFFFFu, p1, m);
            q0 += __shfl_xor_sync(0xFFFFFFFFu, q0, m);
            q1 += __shfl_xor_sync(0xFFFFFFFFu, q1, m);
        }
        if (lane < 4) {
            int lc = wn * 64 + nt * 8 + lane * 2;
            atomicAdd(&ssum[lc], p0);     atomicAdd(&ssq[lc], q0);
            atomicAdd(&ssum[lc + 1], p1); atomicAdd(&ssq[lc + 1], q1);
        }
    }
    __syncthreads();
    if (tid < 128) {
        int col = bn + tid;
        atomicAdd(&stats[col],       (double)ssum[tid]);
        atomicAdd(&stats[256 + col], (double)ssq[tid]);
    }
}

// ---------------- normalize + ELU ----------------
// write_mode: 0 = fp16 gather copy + bf16 root cols (layers 0/1), 1 = fp32 out (final layer)
__global__ void norm_elu_kernel(const float* __restrict__ h,
                                const float* __restrict__ gamma,
                                const float* __restrict__ beta,
                                const double* __restrict__ stats,
                                float* __restrict__ out,
                                int write_mode) {
    __shared__ float sscale[HID];
    __shared__ float sshift[HID];
    int tid = threadIdx.x;   // 256
    {
        double mu  = stats[tid] * (1.0 / N_NODES);
        double var = stats[256 + tid] * (1.0 / N_NODES) - mu * mu;
        float sc = gamma[tid] * rsqrtf((float)var + BN_EPS);
        sscale[tid] = sc;
        sshift[tid] = beta[tid] - (float)mu * sc;
    }
    __syncthreads();
    int r0 = blockIdx.x * 64;
    int r1 = min(r0 + 64, N_NODES);
    float sc = sscale[tid];
    float sh = sshift[tid];
    for (int r = r0; r < r1; r++) {
        size_t idx = (size_t)r * HID + tid;
        float v = h[idx] * sc + sh;
        float o = (v > 0.0f) ? v : expm1f(v);
        if (write_mode == 1) {
            out[idx] = o;
        } else {
            g_rooth[idx] = __float2half_rn(o);
            unsigned short hi, lo;
            split_bf(o, hi, lo);
            size_t a = (size_t)r * 512 + 256 + tid;
            g_Ahi[a] = hi;
            g_Alo[a] = lo;
        }
    }
}

// ---------------- launch ----------------
extern "C" void kernel_launch(void* const* d_in, const int* in_sizes, int n_in,
                              void* d_out, int out_size) {
    (void)in_sizes; (void)n_in; (void)out_size;
    const float* x  = (const float*)d_in[0];
    const int*   ei = (const int*)d_in[1];
    const float* Wn[3] = {(const float*)d_in[2], (const float*)d_in[7],  (const float*)d_in[12]};
    const float* bn[3] = {(const float*)d_in[3], (const float*)d_in[8],  (const float*)d_in[13]};
    const float* Wr[3] = {(const float*)d_in[4], (const float*)d_in[9],  (const float*)d_in[14]};
    const float* gg[3] = {(const float*)d_in[5], (const float*)d_in[10], (const float*)d_in[15]};
    const float* bb[3] = {(const float*)d_in[6], (const float*)d_in[11], (const float*)d_in[16]};
    float* out = (float*)d_out;

    float *h_p;
    double *stats_p;
    unsigned short *Ahi_p, *Alo_p, *Bhi_p, *Blo_p;
    cudaGetSymbolAddress((void**)&h_p,     g_h);
    cudaGetSymbolAddress((void**)&stats_p, g_stats);
    cudaGetSymbolAddress((void**)&Ahi_p,   g_Ahi);
    cudaGetSymbolAddress((void**)&Alo_p,   g_Alo);
    cudaGetSymbolAddress((void**)&Bhi_p,   g_Bhi);
    cudaGetSymbolAddress((void**)&Blo_p,   g_Blo);

    cudaFuncSetAttribute(hmma_gemm_kernel<256>, cudaFuncAttributeMaxDynamicSharedMemorySize, SM_GEMM);
    cudaFuncSetAttribute(hmma_gemm_kernel<512>, cudaFuncAttributeMaxDynamicSharedMemorySize, SM_GEMM);

    const int TB = 256;
    const int nb_nodes = (N_NODES + TB - 1) / TB;
    const int nb_edges = (N_EDGES + TB - 1) / TB;
    const int agg_blocks = (N_NODES * 32 + TB - 1) / TB;
    const int cx_blocks  = (N_NODES * 32 + TB - 1) / TB;
    const int norm_blocks = (N_NODES + 63) / 64;
    dim3 gemm_grid((N_NODES + 127) / 128, 2);
    const int cw_blocks_0  = (HID * 256 + TB - 1) / TB;
    const int cw_blocks_12 = (HID * 512 + TB - 1) / TB;

    // ---- CSR build + zeroing ----
    prep_kernel<<<nb_nodes, TB>>>();
    count_kernel<<<nb_edges, TB>>>(ei);
    scan1_kernel<<<SCAN_NB, 1024>>>();
    scan2_kernel<<<1, 64>>>();
    scan3_kernel<<<SCAN_NB, 1024>>>();
    scatter_kernel<<<nb_edges, TB>>>(ei);

    // ---- layer 0 (DIN=128, KT=256) ----
    convert_x_kernel<<<cx_blocks, TB>>>(x);
    agg0_kernel<<<agg_blocks, TB>>>();
    convert_w_kernel<F_INDIM, 256><<<cw_blocks_0, TB>>>(Wn[0], Wr[0]);
    hmma_gemm_kernel<256><<<gemm_grid, 256, SM_GEMM>>>(Ahi_p, Alo_p, Bhi_p, Blo_p, bn[0], h_p, stats_p);
    norm_elu_kernel<<<norm_blocks, HID>>>(h_p, gg[0], bb[0], stats_p, nullptr, 0);

    // ---- layer 1 (DIN=256, KT=512) ----
    agg_bf_kernel<<<agg_blocks, TB>>>();
    convert_w_kernel<HID, 512><<<cw_blocks_12, TB>>>(Wn[1], Wr[1]);
    hmma_gemm_kernel<512><<<gemm_grid, 256, SM_GEMM>>>(Ahi_p, Alo_p, Bhi_p, Blo_p, bn[1], h_p, stats_p + 512);
    norm_elu_kernel<<<norm_blocks, HID>>>(h_p, gg[1], bb[1], stats_p + 512, nullptr, 0);

    // ---- layer 2 (DIN=256, KT=512) ----
    agg_bf_kernel<<<agg_blocks, TB>>>();
    convert_w_kernel<HID, 512><<<cw_blocks_12, TB>>>(Wn[2], Wr[2]);
    hmma_gemm_kernel<512><<<gemm_grid, 256, SM_GEMM>>>(Ahi_p, Alo_p, Bhi_p, Blo_p, bn[2], out, stats_p + 1024);
    norm_elu_kernel<<<norm_blocks, HID>>>(out, gg[2], bb[2], stats_p + 1024, out, 1);
}

// round 11
// speedup vs baseline: 3.0944x; 1.4967x over previous
#include <cuda_runtime.h>
#include <cuda_fp16.h>
#include <math.h>
#include <stdint.h>

#define N_NODES 50000
#define N_EDGES 800000
#define F_INDIM 128
#define HID 256
#define BN_EPS 1e-5f
#define SCAN_NB 49   // ceil(50000/1024)

// ---------------- scratch (device globals: no allocation allowed) ----------------
__device__ int    g_rowptr[N_NODES + 1];
__device__ int    g_cursor[N_NODES];
__device__ int    g_bsum[64];
__device__ int    g_col[N_EDGES];
__device__ float  g_h[(size_t)N_NODES * HID];          // pre-BN activations (fp32)
__device__ __half g_A[(size_t)N_NODES * 512];          // fp16 A: cols[0:256)=agg, [256:512)=root/gather
__device__ __half g_B[(size_t)HID * 512];              // fp16 B = [Wn;Wr]^T, row stride 512
__device__ double g_stats[3 * 512];                    // per layer: [0:256)=sum, [256:512)=sumsq

// ---------------- small helpers ----------------
__device__ __forceinline__ uint32_t smem_u32(const void* p) {
    uint32_t a;
    asm("{ .reg .u64 t; cvta.to.shared.u64 t, %1; cvt.u32.u64 %0, t; }" : "=r"(a) : "l"(p));
    return a;
}
__device__ __forceinline__ void cp16(uint32_t dst, const void* src) {
    asm volatile("cp.async.cg.shared.global [%0], [%1], 16;" :: "r"(dst), "l"(src) : "memory");
}
__device__ __forceinline__ void cpa_commit() {
    asm volatile("cp.async.commit_group;" ::: "memory");
}
template <int NN>
__device__ __forceinline__ void cpa_wait() {
    asm volatile("cp.async.wait_group %0;" :: "n"(NN) : "memory");
}
__device__ __forceinline__ void ldm_x4(uint32_t* r, uint32_t addr) {
    asm volatile("ldmatrix.sync.aligned.m8n8.x4.shared.b16 {%0,%1,%2,%3}, [%4];"
                 : "=r"(r[0]), "=r"(r[1]), "=r"(r[2]), "=r"(r[3]) : "r"(addr));
}
__device__ __forceinline__ void mma_fp16(float* d, const uint32_t* a, const uint32_t* b) {
    asm volatile("mma.sync.aligned.m16n8k16.row.col.f32.f16.f16.f32 "
                 "{%0,%1,%2,%3}, {%4,%5,%6,%7}, {%8,%9}, {%0,%1,%2,%3};"
                 : "+f"(d[0]), "+f"(d[1]), "+f"(d[2]), "+f"(d[3])
                 : "r"(a[0]), "r"(a[1]), "r"(a[2]), "r"(a[3]), "r"(b[0]), "r"(b[1]));
}

// ---------------- prep: zero edge counters + all 3 stats buffers ----------------
__global__ void prep_kernel() {
    int i = blockIdx.x * blockDim.x + threadIdx.x;
    if (i < N_NODES) g_cursor[i] = 0;
    if (i < 3 * 512) g_stats[i] = 0.0;
}
__global__ void count_kernel(const int* __restrict__ ei) {
    int e = blockIdx.x * blockDim.x + threadIdx.x;
    if (e < N_EDGES) atomicAdd(&g_cursor[ei[N_EDGES + e]], 1);
}
// ---- multi-block scan: phase 1 (per-block exclusive scan + block sums) ----
__global__ void scan1_kernel() {
    __shared__ int sh[1024];
    int tid = threadIdx.x;
    int i = blockIdx.x * 1024 + tid;
    int v = (i < N_NODES) ? g_cursor[i] : 0;
    sh[tid] = v;
    __syncthreads();
    for (int off = 1; off < 1024; off <<= 1) {
        int t = (tid >= off) ? sh[tid - off] : 0;
        __syncthreads();
        sh[tid] += t;
        __syncthreads();
    }
    if (i < N_NODES) g_rowptr[i] = sh[tid] - v;     // local exclusive
    if (tid == 1023) g_bsum[blockIdx.x] = sh[1023];
}
// ---- phase 2: scan the 49 block sums ----
__global__ void scan2_kernel() {
    __shared__ int sh[64];
    int tid = threadIdx.x;
    int v = (tid < SCAN_NB) ? g_bsum[tid] : 0;
    sh[tid] = v;
    __syncthreads();
    for (int off = 1; off < 64; off <<= 1) {
        int t = (tid >= off) ? sh[tid - off] : 0;
        __syncthreads();
        sh[tid] += t;
        __syncthreads();
    }
    if (tid < SCAN_NB) g_bsum[tid] = sh[tid] - v;
    if (tid == 63) g_rowptr[N_NODES] = sh[63];
}
// ---- phase 3: add block offsets, init cursor ----
__global__ void scan3_kernel() {
    int i = blockIdx.x * 1024 + threadIdx.x;
    if (i < N_NODES) {
        int r = g_rowptr[i] + g_bsum[blockIdx.x];
        g_rowptr[i] = r;
        g_cursor[i] = r;
    }
}
__global__ void scatter_kernel(const int* __restrict__ ei) {
    int e = blockIdx.x * blockDim.x + threadIdx.x;
    if (e < N_EDGES) {
        int s = ei[e];
        int d = ei[N_EDGES + e];
        g_col[atomicAdd(&g_cursor[d], 1)] = s;
    }
}

// ---------------- convert x -> fp16 root cols A[:,128:256) ----------------
__global__ void convert_x_kernel(const float* __restrict__ x) {
    int i = blockIdx.x * blockDim.x + threadIdx.x;     // over N*32
    if (i >= N_NODES * 32) return;
    int row = i >> 5, grp = i & 31;
    const float4 v = __ldg((const float4*)(x + (size_t)row * 128 + grp * 4));
    __half2 h01 = __floats2half2_rn(v.x, v.y);
    __half2 h23 = __floats2half2_rn(v.z, v.w);
    uint2 u;
    u.x = *reinterpret_cast<uint32_t*>(&h01);
    u.y = *reinterpret_cast<uint32_t*>(&h23);
    *(uint2*)(g_A + (size_t)row * 512 + 128 + grp * 4) = u;
}

// ---------------- layer0 aggregation: gather x (cols 128-255), write agg cols 0-127 ----------------
__global__ void agg0_kernel() {
    int gw   = (blockIdx.x * blockDim.x + threadIdx.x) >> 5;
    int lane = threadIdx.x & 31;
    if (gw >= N_NODES) return;
    int beg = g_rowptr[gw];
    int end = g_rowptr[gw + 1];

    float a[4] = {0.f, 0.f, 0.f, 0.f};
    for (int e = beg; e < end; e++) {
        int s = g_col[e];
        uint2 u = __ldg((const uint2*)(g_A + (size_t)s * 512 + 128) + lane);
        __half2 h01 = *reinterpret_cast<__half2*>(&u.x);
        __half2 h23 = *reinterpret_cast<__half2*>(&u.y);
        float2 f01 = __half22float2(h01);
        float2 f23 = __half22float2(h23);
        a[0] += f01.x; a[1] += f01.y; a[2] += f23.x; a[3] += f23.y;
    }
    float inv = 1.0f / fmaxf((float)(end - beg), 1.0f);
    __half2 o01 = __floats2half2_rn(a[0] * inv, a[1] * inv);
    __half2 o23 = __floats2half2_rn(a[2] * inv, a[3] * inv);
    uint2 u;
    u.x = *reinterpret_cast<uint32_t*>(&o01);
    u.y = *reinterpret_cast<uint32_t*>(&o23);
    *(uint2*)(g_A + (size_t)gw * 512 + lane * 4) = u;
}

// ---------------- layers 1/2 aggregation: gather root cols 256-511, write agg cols 0-255 ----------------
__global__ void agg_bf_kernel() {
    int gw   = (blockIdx.x * blockDim.x + threadIdx.x) >> 5;
    int lane = threadIdx.x & 31;
    if (gw >= N_NODES) return;
    int beg = g_rowptr[gw];
    int end = g_rowptr[gw + 1];

    float a[8] = {0.f, 0.f, 0.f, 0.f, 0.f, 0.f, 0.f, 0.f};
    for (int e = beg; e < end; e++) {
        int s = g_col[e];
        uint4 u = __ldg((const uint4*)(g_A + (size_t)s * 512 + 256) + lane);   // 8 halves
        __half2 h0 = *reinterpret_cast<__half2*>(&u.x);
        __half2 h1 = *reinterpret_cast<__half2*>(&u.y);
        __half2 h2 = *reinterpret_cast<__half2*>(&u.z);
        __half2 h3 = *reinterpret_cast<__half2*>(&u.w);
        float2 f0 = __half22float2(h0), f1 = __half22float2(h1);
        float2 f2 = __half22float2(h2), f3 = __half22float2(h3);
        a[0] += f0.x; a[1] += f0.y; a[2] += f1.x; a[3] += f1.y;
        a[4] += f2.x; a[5] += f2.y; a[6] += f3.x; a[7] += f3.y;
    }
    float inv = 1.0f / fmaxf((float)(end - beg), 1.0f);
    __half2 o0 = __floats2half2_rn(a[0] * inv, a[1] * inv);
    __half2 o1 = __floats2half2_rn(a[2] * inv, a[3] * inv);
    __half2 o2 = __floats2half2_rn(a[4] * inv, a[5] * inv);
    __half2 o3 = __floats2half2_rn(a[6] * inv, a[7] * inv);
    uint4 u;
    u.x = *reinterpret_cast<uint32_t*>(&o0);
    u.y = *reinterpret_cast<uint32_t*>(&o1);
    u.z = *reinterpret_cast<uint32_t*>(&o2);
    u.w = *reinterpret_cast<uint32_t*>(&o3);
    *(uint4*)(g_A + (size_t)gw * 512 + lane * 8) = u;
}

// ---------------- convert weights: B[n][k] = (k<DIN ? Wn[k][n] : Wr[k-DIN][n]), fp16 ----------------
template <int DIN, int KEXT>
__global__ void convert_w_kernel(const float* __restrict__ Wn, const float* __restrict__ Wr) {
    int i = blockIdx.x * blockDim.x + threadIdx.x;    // over 256*KEXT
    if (i >= HID * KEXT) return;
    int n = i / KEXT, k = i % KEXT;
    float w = (k < DIN) ? Wn[(size_t)k * HID + n] : Wr[(size_t)(k - DIN) * HID + n];
    g_B[(size_t)n * 512 + k] = __float2half_rn(w);
}

// ---------------- fp16 HMMA GEMM with fused BN-stats epilogue ----------------
// CTA tile 128x128, 8 warps (4x2), warp tile 32x64, K-chunk 32, double-buffered cp.async.
#define SA 40                        // smem halves per row (32 + 8 pad)
#define OF_B 10240u
#define BUFB 20480u
#define SM_GEMM (2 * 20480)

template <int KT>   // k-extent: 256 (layer0) or 512; row stride is always 512
__global__ void __launch_bounds__(256, 2)
hmma_gemm_kernel(const __half* __restrict__ A, const __half* __restrict__ B,
                 const float* __restrict__ bias, float* __restrict__ C,
                 double* __restrict__ stats) {
    extern __shared__ char smem[];
    const uint32_t sb = smem_u32(smem);
    const int tid  = threadIdx.x;
    const int lane = tid & 31;
    const int wid  = tid >> 5;
    const int wm   = wid & 3;
    const int wn   = wid >> 2;
    const int bm   = blockIdx.x * 128;
    const int bn   = blockIdx.y * 128;

    float acc[2][8][4];
#pragma unroll
    for (int a = 0; a < 2; a++)
#pragma unroll
        for (int b = 0; b < 8; b++)
#pragma unroll
            for (int c = 0; c < 4; c++) acc[a][b][c] = 0.0f;

    auto issue = [&](int buf, int k0) {
        uint32_t base = sb + buf * BUFB;
#pragma unroll
        for (int v = 0; v < 2; v++) {
            int idx = v * 256 + tid;         // 0..511
            int r = idx >> 2, s = idx & 3;
            int grow = bm + r;
            if (grow >= N_NODES) grow = N_NODES - 1;   // clamp; excluded in epilogue
            size_t goA = (size_t)grow * 512 + k0 + s * 8;
            size_t goB = (size_t)(bn + r) * 512 + k0 + s * 8;
            uint32_t d = base + (uint32_t)(r * SA + s * 8) * 2;
            cp16(d, A + goA);
            cp16(d + OF_B, B + goB);
        }
    };

    const int nch = KT / 32;
    issue(0, 0);
    cpa_commit();
    int buf = 0;
    for (int ch = 0; ch < nch; ch++) {
        if (ch + 1 < nch) {
            issue(buf ^ 1, (ch + 1) * 32);
            cpa_commit();
            cpa_wait<1>();
        } else {
            cpa_wait<0>();
        }
        __syncthreads();
        uint32_t base = sb + buf * BUFB;
#pragma unroll
        for (int ks = 0; ks < 2; ks++) {
            const int kc = ks * 16;
            uint32_t ah[2][4];
#pragma unroll
            for (int mt = 0; mt < 2; mt++) {
                int row = wm * 32 + mt * 16 + (lane & 15);
                int col = kc + ((lane >> 4) << 3);
                ldm_x4(ah[mt], base + (uint32_t)(row * SA + col) * 2);
            }
#pragma unroll
            for (int g = 0; g < 4; g++) {
                int nrow = wn * 64 + g * 16 + ((lane >> 4) << 3) + (lane & 7);
                int kcol = kc + (((lane >> 3) & 1) << 3);
                uint32_t bh4[4];
                ldm_x4(bh4, base + (uint32_t)(nrow * SA + kcol) * 2 + OF_B);
#pragma unroll
                for (int mt = 0; mt < 2; mt++)
#pragma unroll
                    for (int s = 0; s < 2; s++)
                        mma_fp16(acc[mt][g * 2 + s], ah[mt], &bh4[s * 2]);
            }
        }
        __syncthreads();
        buf ^= 1;
    }

    // ---- epilogue: write C (+bias) and fused BN column stats ----
    float* ssum = (float*)smem;
    float* ssq  = ssum + 128;
    if (tid < 128) { ssum[tid] = 0.0f; ssq[tid] = 0.0f; }
    __syncthreads();

#pragma unroll
    for (int nt = 0; nt < 8; nt++) {
        int col = bn + wn * 64 + nt * 8 + (lane & 3) * 2;
        float b0 = __ldg(&bias[col]);
        float b1 = __ldg(&bias[col + 1]);
        float p0 = 0.f, p1 = 0.f, q0 = 0.f, q1 = 0.f;
#pragma unroll
        for (int mt = 0; mt < 2; mt++) {
            int row0 = bm + wm * 32 + mt * 16 + (lane >> 2);
            float c0 = acc[mt][nt][0] + b0;
            float c1 = acc[mt][nt][1] + b1;
            float c2 = acc[mt][nt][2] + b0;
            float c3 = acc[mt][nt][3] + b1;
            if (row0 < N_NODES) {
                C[(size_t)row0 * HID + col]     = c0;
                C[(size_t)row0 * HID + col + 1] = c1;
                p0 += c0; q0 += c0 * c0;
                p1 += c1; q1 += c1 * c1;
            }
            if (row0 + 8 < N_NODES) {
                C[(size_t)(row0 + 8) * HID + col]     = c2;
                C[(size_t)(row0 + 8) * HID + col + 1] = c3;
                p0 += c2; q0 += c2 * c2;
                p1 += c3; q1 += c3 * c3;
            }
        }
#pragma unroll
        for (int m = 4; m < 32; m <<= 1) {
            p0 += __shfl_xor_sync(0xFFFFFFFFu, p0, m);
            p1 += __shfl_xor_sync(0xFFFFFFFFu, p1, m);
            q0 += __shfl_xor_sync(0xFFFFFFFFu, q0, m);
            q1 += __shfl_xor_sync(0xFFFFFFFFu, q1, m);
        }
        if (lane < 4) {
            int lc = wn * 64 + nt * 8 + lane * 2;
            atomicAdd(&ssum[lc], p0);     atomicAdd(&ssq[lc], q0);
            atomicAdd(&ssum[lc + 1], p1); atomicAdd(&ssq[lc + 1], q1);
        }
    }
    __syncthreads();
    if (tid < 128) {
        int col = bn + tid;
        atomicAdd(&stats[col],       (double)ssum[tid]);
        atomicAdd(&stats[256 + col], (double)ssq[tid]);
    }
}

// ---------------- normalize + ELU ----------------
// write_mode: 0 = fp16 root cols of g_A (layers 0/1), 1 = fp32 out (final layer)
__global__ void norm_elu_kernel(const float* __restrict__ h,
                                const float* __restrict__ gamma,
                                const float* __restrict__ beta,
                                const double* __restrict__ stats,
                                float* __restrict__ out,
                                int write_mode) {
    __shared__ float sscale[HID];
    __shared__ float sshift[HID];
    int tid = threadIdx.x;   // 256
    {
        double mu  = stats[tid] * (1.0 / N_NODES);
        double var = stats[256 + tid] * (1.0 / N_NODES) - mu * mu;
        float sc = gamma[tid] * rsqrtf((float)var + BN_EPS);
        sscale[tid] = sc;
        sshift[tid] = beta[tid] - (float)mu * sc;
    }
    __syncthreads();
    int r0 = blockIdx.x * 64;
    int r1 = min(r0 + 64, N_NODES);
    float sc = sscale[tid];
    float sh = sshift[tid];
    for (int r = r0; r < r1; r++) {
        size_t idx = (size_t)r * HID + tid;
        float v = h[idx] * sc + sh;
        float o = (v > 0.0f) ? v : expm1f(v);
        if (write_mode == 1) {
            out[idx] = o;
        } else {
            g_A[(size_t)r * 512 + 256 + tid] = __float2half_rn(o);
        }
    }
}

// ---------------- launch ----------------
extern "C" void kernel_launch(void* const* d_in, const int* in_sizes, int n_in,
                              void* d_out, int out_size) {
    (void)in_sizes; (void)n_in; (void)out_size;
    const float* x  = (const float*)d_in[0];
    const int*   ei = (const int*)d_in[1];
    const float* Wn[3] = {(const float*)d_in[2], (const float*)d_in[7],  (const float*)d_in[12]};
    const float* bn[3] = {(const float*)d_in[3], (const float*)d_in[8],  (const float*)d_in[13]};
    const float* Wr[3] = {(const float*)d_in[4], (const float*)d_in[9],  (const float*)d_in[14]};
    const float* gg[3] = {(const float*)d_in[5], (const float*)d_in[10], (const float*)d_in[15]};
    const float* bb[3] = {(const float*)d_in[6], (const float*)d_in[11], (const float*)d_in[16]};
    float* out = (float*)d_out;

    float *h_p;
    double *stats_p;
    __half *A_p, *B_p;
    cudaGetSymbolAddress((void**)&h_p,     g_h);
    cudaGetSymbolAddress((void**)&stats_p, g_stats);
    cudaGetSymbolAddress((void**)&A_p,     g_A);
    cudaGetSymbolAddress((void**)&B_p,     g_B);

    cudaFuncSetAttribute(hmma_gemm_kernel<256>, cudaFuncAttributeMaxDynamicSharedMemorySize, SM_GEMM);
    cudaFuncSetAttribute(hmma_gemm_kernel<512>, cudaFuncAttributeMaxDynamicSharedMemorySize, SM_GEMM);

    const int TB = 256;
    const int nb_nodes = (N_NODES + TB - 1) / TB;
    const int nb_edges = (N_EDGES + TB - 1) / TB;
    const int agg_blocks = (N_NODES * 32 + TB - 1) / TB;
    const int cx_blocks  = (N_NODES * 32 + TB - 1) / TB;
    const int norm_blocks = (N_NODES + 63) / 64;
    dim3 gemm_grid((N_NODES + 127) / 128, 2);
    const int cw_blocks_0  = (HID * 256 + TB - 1) / TB;
    const int cw_blocks_12 = (HID * 512 + TB - 1) / TB;

    // ---- CSR build + zeroing ----
    prep_kernel<<<nb_nodes, TB>>>();
    count_kernel<<<nb_edges, TB>>>(ei);
    scan1_kernel<<<SCAN_NB, 1024>>>();
    scan2_kernel<<<1, 64>>>();
    scan3_kernel<<<SCAN_NB, 1024>>>();
    scatter_kernel<<<nb_edges, TB>>>(ei);

    // ---- layer 0 (DIN=128, KEXT=256) ----
    convert_x_kernel<<<cx_blocks, TB>>>(x);
    agg0_kernel<<<agg_blocks, TB>>>();
    convert_w_kernel<F_INDIM, 256><<<cw_blocks_0, TB>>>(Wn[0], Wr[0]);
    hmma_gemm_kernel<256><<<gemm_grid, 256, SM_GEMM>>>(A_p, B_p, bn[0], h_p, stats_p);
    norm_elu_kernel<<<norm_blocks, HID>>>(h_p, gg[0], bb[0], stats_p, nullptr, 0);

    // ---- layer 1 (DIN=256, KEXT=512) ----
    agg_bf_kernel<<<agg_blocks, TB>>>();
    convert_w_kernel<HID, 512><<<cw_blocks_12, TB>>>(Wn[1], Wr[1]);
    hmma_gemm_kernel<512><<<gemm_grid, 256, SM_GEMM>>>(A_p, B_p, bn[1], h_p, stats_p + 512);
    norm_elu_kernel<<<norm_blocks, HID>>>(h_p, gg[1], bb[1], stats_p + 512, nullptr, 0);

    // ---- layer 2 (DIN=256, KEXT=512) ----
    agg_bf_kernel<<<agg_blocks, TB>>>();
    convert_w_kernel<HID, 512><<<cw_blocks_12, TB>>>(Wn[2], Wr[2]);
    hmma_gemm_kernel<512><<<gemm_grid, 256, SM_GEMM>>>(A_p, B_p, bn[2], out, stats_p + 1024);
    norm_elu_kernel<<<norm_blocks, HID>>>(out, gg[2], bb[2], stats_p + 1024, out, 1);
}